// round 14
// baseline (speedup 1.0000x reference)
#include <cuda_runtime.h>
#include <cstdint>
#include <math.h>

#define NB 4096
#define NSUP 5
#define NROWS (NB + NSUP)
#define ED 128
#define DM 256
#define DI 512
#define LH 512
#define GR 1024
#define PADI 200000
#define MAXK 64
#define TOPK 10
#define NUNITS (2 * NB + 2 * NSUP)   // 8202
#define PROWS (NUNITS * TOPK)        // 82020
#define PROWS_PAD 82080
#define PTILES ((PROWS + 127) / 128) // 641
#define KPAD 36

// ------------------- device scratch -------------------
__device__ float g_vec[NROWS * DM];
__device__ float g_h1[NROWS * DI];
__device__ float g_enc[NROWS * DM];
__device__ float g_supg[DM];
__device__ float g_rpart[GR];
__device__ float g_bsum[GR];
__device__ float g_xpart[(size_t)NB * GR];
__device__ float g_h[(size_t)NB * DM];
__device__ float g_hB[(size_t)NB * DM];
__device__ float g_c[(size_t)NB * DM];
__device__ float g_wihR[GR * DM];
__device__ float g_whhR[GR * DM];
__device__ float g_p1R[DI * DM];
__device__ float g_p2R[DM * DI];
__device__ float g_gcnR[ED * DM];
__device__ int   g_rowids[PROWS_PAD * 2];
__device__ int4  g_uinfo[8208];
__device__ float g_proj[(size_t)(PTILES * 128) * ED];

__device__ __forceinline__ float warp_sum(float v) {
#pragma unroll
    for (int o = 16; o; o >>= 1) v += __shfl_xor_sync(0xffffffffu, v, o);
    return v;
}
__device__ __forceinline__ float sigf(float x) { return 1.0f / (1.0f + expf(-x)); }
__device__ __forceinline__ float tf32r(float v) {
    uint32_t r;
    asm("cvt.rna.tf32.f32 %0, %1;" : "=r"(r) : "f"(v));
    return __uint_as_float(r);
}
__device__ __forceinline__ void mma_tf32(float* c, const uint32_t* a, const uint32_t* b) {
    asm volatile(
        "mma.sync.aligned.m16n8k8.row.col.f32.tf32.tf32.f32 "
        "{%0,%1,%2,%3}, {%4,%5,%6,%7}, {%8,%9}, {%0,%1,%2,%3};"
        : "+f"(c[0]), "+f"(c[1]), "+f"(c[2]), "+f"(c[3])
        : "r"(a[0]), "r"(a[1]), "r"(a[2]), "r"(a[3]), "r"(b[0]), "r"(b[1]));
}
__device__ __forceinline__ void cp_async16(uint32_t s, const void* g, int sz) {
    asm volatile("cp.async.cg.shared.global [%0], [%1], 16, %2;\n"
                 :: "r"(s), "l"(g), "r"(sz));
}
__device__ __forceinline__ void cp_commit() { asm volatile("cp.async.commit_group;\n"); }
__device__ __forceinline__ void cp_wait1() { asm volatile("cp.async.wait_group 1;\n"); }
__device__ __forceinline__ void cp_wait0() { asm volatile("cp.async.wait_group 0;\n"); }

__device__ __forceinline__ int permN(int n) {
    return (((n >> 3) & 3) << 9) + ((n >> 5) << 3) + (n & 7);
}

__device__ __forceinline__ void unit_decode(
    int ur,
    const int* qry, const int* sup,
    const int* q_l1, const int* q_deg_l, const int* q_r1, const int* q_deg_r,
    const int* s_l1, const int* s_deg_l, const int* s_r1, const int* s_deg_r,
    const int** conn, int* deg, int* selfid, size_t* outoff) {
    if (ur < NB) {
        *conn = q_l1 + ur * MAXK * 2; *deg = q_deg_l[ur];
        *selfid = qry[ur * 2 + 0]; *outoff = (size_t)ur * DM;
    } else if (ur < 2 * NB) {
        int b = ur - NB;
        *conn = q_r1 + b * MAXK * 2; *deg = q_deg_r[b];
        *selfid = qry[b * 2 + 1]; *outoff = (size_t)b * DM + ED;
    } else if (ur < 2 * NB + NSUP) {
        int i = ur - 2 * NB;
        *conn = s_l1 + i * MAXK * 2; *deg = s_deg_l[i];
        *selfid = sup[i * 2 + 0]; *outoff = (size_t)(NB + i) * DM;
    } else {
        int i = ur - 2 * NB - NSUP;
        *conn = s_r1 + i * MAXK * 2; *deg = s_deg_r[i];
        *selfid = sup[i * 2 + 1]; *outoff = (size_t)(NB + i) * DM + ED;
    }
}

// ------------------- prep: everything merged (FIXED region boundaries) -------------------
#define PREP_GCN 128
#define PREP_B (PREP_GCN + 4)
#define PREP_PAD (PREP_B + 1)
#define PREP_WIH (PREP_PAD + 1 + GR)            // wih region: [PREP_PAD+1, PREP_WIH)
#define PREP_WHH (PREP_WIH + GR)                // whh region: [PREP_WIH, PREP_WHH)
#define PREP_P1 (PREP_WHH + DI * DM / 256)      // p1 region: [PREP_WHH, PREP_P1) = 512 blocks
#define PREP_P2 (PREP_P1 + DM * DI / 256)       // p2 region: [PREP_P1, PREP_P2) = 512 blocks
__global__ void prep_kernel(const float* __restrict__ gcn,
                            const float* __restrict__ b_ih,
                            const float* __restrict__ b_hh,
                            const float* __restrict__ w_ih,
                            const float* __restrict__ w_hh,
                            const float* __restrict__ p1,
                            const float* __restrict__ p2) {
    int t = threadIdx.x, b = blockIdx.x;
    if (b < PREP_GCN) {
        int i = b * 256 + t;
        g_gcnR[i] = tf32r(gcn[i]);
    } else if (b < PREP_B) {
        int n = (b - PREP_GCN) * 256 + t;
        int p = permN(n);
        g_bsum[n] = b_ih[p] + b_hh[p];
    } else if (b < PREP_PAD) {
        if (t < (PROWS_PAD - PROWS) * 2) g_rowids[PROWS * 2 + t] = 0;
    } else if (b < PREP_WIH) {
        int n = b - (PREP_PAD + 1) + 1;  // careful: region starts at PREP_PAD
        n = b - PREP_PAD;                // n in [0, GR)... region is [PREP_PAD, PREP_PAD+GR)
        if (n < GR)
            g_wihR[n * DM + t] = tf32r(w_ih[permN(n) * DM + t]);
    } else if (b < PREP_WHH) {
        int n = b - PREP_WIH;
        g_whhR[n * DM + t] = tf32r(w_hh[(size_t)permN(n) * LH + t]);
    } else if (b < PREP_P1) {
        int i = (b - PREP_WHH) * 256 + t;
        g_p1R[i] = tf32r(p1[i]);
    } else if (b < PREP_P2) {
        int i = (b - PREP_P1) * 256 + t;
        g_p2R[i] = tf32r(p2[i]);
    }
}
__global__ void zeroout_kernel(float* __restrict__ out) {
    out[blockIdx.x * 256 + threadIdx.x] = 0.f;
}

// ------------------- phase 1: sims + top-10 -------------------
__global__ void __launch_bounds__(128)
topk_kernel(const int* __restrict__ qry, const int* __restrict__ sup,
            const int* __restrict__ q_l1, const int* __restrict__ q_deg_l,
            const int* __restrict__ q_r1, const int* __restrict__ q_deg_r,
            const int* __restrict__ s_l1, const int* __restrict__ s_deg_l,
            const int* __restrict__ s_r1, const int* __restrict__ s_deg_r,
            const float* __restrict__ emb) {
    __shared__ float s_selfn[ED];
    __shared__ float s_sim[MAXK];
    __shared__ int s_rel[MAXK], s_ent[MAXK];
    __shared__ float s_red[4];
    __shared__ float s_sc[1];

    int unit = blockIdx.x, tid = threadIdx.x;
    int lane = tid & 31, warp = tid >> 5;

    const int* conn; int deg, selfid; size_t outoff;
    unit_decode(unit, qry, sup, q_l1, q_deg_l, q_r1, q_deg_r,
                s_l1, s_deg_l, s_r1, s_deg_r, &conn, &deg, &selfid, &outoff);

    float se = emb[(size_t)selfid * ED + tid];
    float ss = warp_sum(se * se);
    if (lane == 0) s_red[warp] = ss;
    __syncthreads();
    if (tid == 0)
        s_sc[0] = 1.0f / fmaxf(sqrtf(s_red[0] + s_red[1] + s_red[2] + s_red[3]), 1e-12f);
    __syncthreads();
    s_selfn[tid] = se * s_sc[0];
    __syncthreads();

    int gid = lane >> 3, gl = lane & 7;
    float4 sn[4];
#pragma unroll
    for (int q = 0; q < 4; q++) sn[q] = ((const float4*)s_selfn)[gl + 8 * q];

#pragma unroll
    for (int jt = 0; jt < 4; jt++) {
        int j = warp * 16 + jt * 4 + gid;
        int2 ids = ((const int2*)conn)[j];
        const float4* er = (const float4*)(emb + (size_t)ids.y * ED);
        float dot = 0.f, sq = 0.f;
#pragma unroll
        for (int q = 0; q < 4; q++) {
            float4 e = er[gl + 8 * q];
            dot += e.x * sn[q].x + e.y * sn[q].y + e.z * sn[q].z + e.w * sn[q].w;
            sq += e.x * e.x + e.y * e.y + e.z * e.z + e.w * e.w;
        }
#pragma unroll
        for (int o = 4; o; o >>= 1) {
            unsigned long long v =
                ((unsigned long long)__float_as_uint(sq) << 32) | __float_as_uint(dot);
            unsigned long long w = __shfl_xor_sync(0xffffffffu, v, o);
            dot += __uint_as_float((uint32_t)w);
            sq += __uint_as_float((uint32_t)(w >> 32));
        }
        if (gl == 0) {
            float sim = dot / fmaxf(sqrtf(sq), 1e-12f);
            if (ids.x == PADI) sim -= 1e9f;
            s_sim[j] = sim; s_rel[j] = ids.x; s_ent[j] = ids.y;
        }
    }
    __syncthreads();

    if (warp == 0) {
        float v0 = s_sim[lane], v1 = s_sim[lane + 32];
        int nv = 0, mask = 0;
#pragma unroll
        for (int t = 0; t < TOPK; t++) {
            float mv = v0; int mi = lane;
            if (v1 > mv) { mv = v1; mi = lane + 32; }
#pragma unroll
            for (int o = 16; o; o >>= 1) {
                float ov = __shfl_xor_sync(0xffffffffu, mv, o);
                int oi = __shfl_xor_sync(0xffffffffu, mi, o);
                if (ov > mv || (ov == mv && oi < mi)) { mv = ov; mi = oi; }
            }
            if (lane == 0) {
                int rel = s_rel[mi], ent = s_ent[mi];
                g_rowids[(unit * TOPK + t) * 2 + 0] = rel;
                g_rowids[(unit * TOPK + t) * 2 + 1] = ent;
                if (rel == PADI) mask |= (1 << t); else nv++;
            }
            if (mi == lane) v0 = -3.0e38f;
            if (mi == lane + 32) v1 = -3.0e38f;
        }
        if (lane == 0) g_uinfo[unit] = make_int4(selfid, deg, nv, mask);
    }
}

// ------------------- phase 2: gathered proj GEMM (prefetch-first, wait1) -------------------
__global__ void __launch_bounds__(256, 2)
projgather_kernel(const float* __restrict__ emb,
                  const float* __restrict__ gcn_w_b,
                  const float* __restrict__ gcn_b) {
    __shared__ float As[3][128][KPAD];
    __shared__ float Bs[3][128][KPAD];
    __shared__ int2 s_ids[128];

    int tid = threadIdx.x;
    int m0 = blockIdx.x << 7;
    int lane = tid & 31, warp = tid >> 5;
    int wm = warp >> 2, wn = warp & 3;
    int r = lane >> 2, cq = lane & 3;

    uint32_t sA = (uint32_t)__cvta_generic_to_shared(&As[0][0][0]);
    uint32_t sB = (uint32_t)__cvta_generic_to_shared(&Bs[0][0][0]);
    const uint32_t strAB = 128 * KPAD * 4;

    if (tid < 128) s_ids[tid] = ((const int2*)g_rowids)[m0 + tid];
    __syncthreads();

    float acc[4][4][4];
#pragma unroll
    for (int i = 0; i < 4; i++)
#pragma unroll
        for (int j = 0; j < 4; j++)
#pragma unroll
            for (int q = 0; q < 4; q++) acc[i][j][q] = 0.f;

    auto stage = [&](int buf, int k0) {
        bool lo = (k0 < ED);
#pragma unroll
        for (int i = 0; i < 4; i++) {
            int seg = tid + i * 256;
            int row = seg >> 3, k4 = (seg & 7) << 2;
            int2 ids = s_ids[row];
            const float* srcA = emb + (size_t)(lo ? ids.x : ids.y) * ED
                                + (lo ? k0 : k0 - ED) + k4;
            cp_async16(sA + buf * strAB + (row * KPAD + k4) * 4, srcA, 16);
            cp_async16(sB + buf * strAB + (row * KPAD + k4) * 4,
                       g_gcnR + row * DM + k0 + k4, 16);
        }
        cp_commit();
    };

    stage(0, 0);
    stage(1, 32);
    int buf = 0;
    for (int kt = 0; kt < 8; kt++) {
        if (kt == 7) cp_wait0(); else cp_wait1();
        __syncthreads();
        // prefetch first: tile kt+2 copy overlaps this iteration's MMAs
        if (kt + 2 < 8) stage(buf + 2 >= 3 ? buf - 1 : buf + 2, (kt + 2) << 5);

        const float (*Ab)[KPAD] = As[buf];
        const float (*Bb)[KPAD] = Bs[buf];
#pragma unroll
        for (int ks = 0; ks < 4; ks++) {
            int kb = ks * 8;
            uint32_t a[4][4];
#pragma unroll
            for (int am = 0; am < 4; am++) {
                int row = wm * 64 + am * 16 + r;
                a[am][0] = __float_as_uint(Ab[row][kb + cq]);
                a[am][1] = __float_as_uint(Ab[row + 8][kb + cq]);
                a[am][2] = __float_as_uint(Ab[row][kb + cq + 4]);
                a[am][3] = __float_as_uint(Ab[row + 8][kb + cq + 4]);
            }
            uint32_t b[4][2];
#pragma unroll
            for (int an = 0; an < 4; an++) {
                int nrow = wn * 32 + an * 8 + r;
                b[an][0] = __float_as_uint(Bb[nrow][kb + cq]);
                b[an][1] = __float_as_uint(Bb[nrow][kb + cq + 4]);
            }
#pragma unroll
            for (int am = 0; am < 4; am++)
#pragma unroll
                for (int an = 0; an < 4; an++)
                    mma_tf32(acc[am][an], a[am], b[an]);
        }
        buf = (buf == 2) ? 0 : buf + 1;
    }

#pragma unroll
    for (int am = 0; am < 4; am++) {
        int rw0 = m0 + wm * 64 + am * 16 + r;
        int rw1 = rw0 + 8;
#pragma unroll
        for (int an = 0; an < 4; an++) {
            int col = wn * 32 + an * 8 + cq * 2;
            float b0 = gcn_w_b[col] + gcn_b[col];
            float b1 = gcn_w_b[col + 1] + gcn_b[col + 1];
            if (rw0 < PROWS) {
                float v0 = acc[am][an][0] + b0;
                float v1 = acc[am][an][1] + b1;
                v0 = v0 > 0.f ? v0 : 0.01f * v0;
                v1 = v1 > 0.f ? v1 : 0.01f * v1;
                g_proj[(size_t)rw0 * ED + col] = v0;
                g_proj[(size_t)rw0 * ED + col + 1] = v1;
            }
            if (rw1 < PROWS) {
                float v2 = acc[am][an][2] + b0;
                float v3 = acc[am][an][3] + b1;
                v2 = v2 > 0.f ? v2 : 0.01f * v2;
                v3 = v3 > 0.f ? v3 : 0.01f * v3;
                g_proj[(size_t)rw1 * ED + col] = v2;
                g_proj[(size_t)rw1 * ED + col + 1] = v3;
            }
        }
    }
}

// ------------------- phase 3: warp-per-unit agg + gate MLP + output -------------------
#define AW 8
#define AUPW 4
__global__ void __launch_bounds__(256)
agg_gate_kernel(const int* __restrict__ qry, const int* __restrict__ sup,
                const int* __restrict__ q_l1, const int* __restrict__ q_deg_l,
                const int* __restrict__ q_r1, const int* __restrict__ q_deg_r,
                const int* __restrict__ s_l1, const int* __restrict__ s_deg_l,
                const int* __restrict__ s_r1, const int* __restrict__ s_deg_r,
                const float* __restrict__ emb,
                const float* __restrict__ g1_w, const float* __restrict__ g1_b,
                const float* __restrict__ ln1_g, const float* __restrict__ ln1_b,
                const float* __restrict__ g2_w, const float* __restrict__ g2_b,
                const float* __restrict__ gate_temp) {
    __shared__ float4 s_g1[64 * 32];
    __shared__ float4 s_agg[AW][33];
    __shared__ float s_b[64], s_lg[64], s_lb[64], s_g2[64];
    __shared__ float s_scal[2];

    int tid = threadIdx.x;
    int lane = tid & 31, warp = tid >> 5;

#pragma unroll
    for (int i = 0; i < 8; i++) {
        int f = tid + i * 256;
        int d = f >> 5, g = f & 31;
        s_g1[d * 32 + (g ^ (d & 7))] = ((const float4*)g1_w)[f];
    }
    if (tid < 64) {
        s_b[tid] = g1_b[tid]; s_lg[tid] = ln1_g[tid];
        s_lb[tid] = ln1_b[tid]; s_g2[tid] = g2_w[tid];
    }
    if (tid == 0) {
        s_scal[0] = g2_b[0];
        s_scal[1] = 1.0f / fminf(fmaxf(gate_temp[0], 0.1f), 5.0f);
    }
    __syncthreads();

    float g2b = s_scal[0], invT = s_scal[1];

    for (int u = 0; u < AUPW; u++) {
        int unit = (blockIdx.x * AW + warp) * AUPW + u;
        if (unit >= NUNITS) break;
        int4 info = g_uinfo[unit];

        const float4* pr = (const float4*)(g_proj + (size_t)unit * TOPK * ED);
        float4 a = make_float4(0.f, 0.f, 0.f, 0.f);
#pragma unroll
        for (int j = 0; j < TOPK; j++) {
            if (!((info.w >> j) & 1)) {
                float4 p = pr[j * 32 + lane];
                a.x += p.x; a.y += p.y; a.z += p.z; a.w += p.w;
            }
        }
        float inv = 1.0f / fmaxf((float)info.z, 1.0f);
        a.x *= inv; a.y *= inv; a.z *= inv; a.w *= inv;
        s_agg[warp][lane] = a;
        __syncwarp();

        float y0 = s_b[lane], y1 = s_b[lane + 32];
        int sw = lane & 7;
        const float4* w0 = &s_g1[lane * 32];
        const float4* w1 = &s_g1[(lane + 32) * 32];
#pragma unroll
        for (int k = 0; k < 32; k++) {
            float4 av = s_agg[warp][k];
            float4 a0 = w0[k ^ sw];
            float4 a1 = w1[k ^ sw];
            y0 += av.x * a0.x + av.y * a0.y + av.z * a0.z + av.w * a0.w;
            y1 += av.x * a1.x + av.y * a1.y + av.z * a1.z + av.w * a1.w;
        }

        float s1 = warp_sum(y0 + y1);
        float s2 = warp_sum(y0 * y0 + y1 * y1);
        float mean = s1 * (1.0f / 64.0f);
        float var = s2 * (1.0f / 64.0f) - mean * mean;
        float rstd = rsqrtf(var + 1e-5f);
        float hv0 = fmaxf((y0 - mean) * rstd * s_lg[lane] + s_lb[lane], 0.f);
        float hv1 = fmaxf((y1 - mean) * rstd * s_lg[lane + 32] + s_lb[lane + 32], 0.f);
        float logit = warp_sum(hv0 * s_g2[lane] + hv1 * s_g2[lane + 32]) + g2b;
        float gate = 1.0f / (1.0f + expf(-logit * invT));
        if (info.y <= 0) gate = 0.f;

        const int* conn; int deg, selfid; size_t outoff;
        unit_decode(unit, qry, sup, q_l1, q_deg_l, q_r1, q_deg_r,
                    s_l1, s_deg_l, s_r1, s_deg_r, &conn, &deg, &selfid, &outoff);
        float4 e = ((const float4*)(emb + (size_t)info.x * ED))[lane];
        float4 o;
        o.x = tf32r(tanhf(e.x + gate * a.x));
        o.y = tf32r(tanhf(e.y + gate * a.y));
        o.z = tf32r(tanhf(e.z + gate * a.z));
        o.w = tf32r(tanhf(e.w + gate * a.w));
        *(float4*)(g_vec + outoff + lane * 4) = o;
        __syncwarp();
    }
}

// ------------------- TF32 GEMM (prefetch-first 3-stage, wait1) + fused LSTM cell -------------------
template<int BMT, int MODE>
__global__ void __launch_bounds__(256, 2)
gemm_v3(const float* __restrict__ A, int lda,
        const float* __restrict__ W, int ldw,
        const float* __restrict__ bias,
        const float* __restrict__ base,
        const float* __restrict__ rowv,
        float* __restrict__ C, int ldc,
        int M, int N, int K, int act, int roundOut,
        float* __restrict__ hOut, int lastStep) {
    constexpr int AMT = BMT / 32;
    constexpr int ASEG = BMT * 8 / 256;
    __shared__ float As[3][BMT][KPAD];
    __shared__ float Bs[3][128][KPAD];

    int tid = threadIdx.x;
    int m0 = blockIdx.y * BMT, n0 = blockIdx.x << 7;
    int lane = tid & 31, warp = tid >> 5;
    int wm = warp >> 2, wn = warp & 3;
    int r = lane >> 2, cq = lane & 3;

    uint32_t sA = (uint32_t)__cvta_generic_to_shared(&As[0][0][0]);
    uint32_t sB = (uint32_t)__cvta_generic_to_shared(&Bs[0][0][0]);
    const uint32_t strA = BMT * KPAD * 4;
    const uint32_t strB = 128 * KPAD * 4;

    float acc[AMT][4][4];
#pragma unroll
    for (int i = 0; i < AMT; i++)
#pragma unroll
        for (int j = 0; j < 4; j++)
#pragma unroll
            for (int q = 0; q < 4; q++) acc[i][j][q] = 0.f;

    int KT = K >> 5;

    auto stage = [&](int buf, int k0) {
#pragma unroll
        for (int i = 0; i < ASEG; i++) {
            int seg = tid + i * 256;
            int row = seg >> 3, k4 = (seg & 7) << 2;
            int m = m0 + row;
            cp_async16(sA + buf * strA + (row * KPAD + k4) * 4,
                       A + (size_t)m * lda + k0 + k4, m < M ? 16 : 0);
        }
#pragma unroll
        for (int i = 0; i < 4; i++) {
            int seg = tid + i * 256;
            int row = seg >> 3, k4 = (seg & 7) << 2;
            cp_async16(sB + buf * strB + (row * KPAD + k4) * 4,
                       W + (size_t)(n0 + row) * ldw + k0 + k4, 16);
        }
        cp_commit();
    };

    stage(0, 0);
    stage(1, 32);
    int buf = 0;
    for (int kt = 0; kt < KT; kt++) {
        if (kt == KT - 1) cp_wait0(); else cp_wait1();
        __syncthreads();
        if (kt + 2 < KT) stage(buf + 2 >= 3 ? buf - 1 : buf + 2, (kt + 2) << 5);

        const float (*Ab)[KPAD] = As[buf];
        const float (*Bb)[KPAD] = Bs[buf];
#pragma unroll
        for (int ks = 0; ks < 4; ks++) {
            int kb = ks * 8;
            uint32_t a[AMT][4];
#pragma unroll
            for (int am = 0; am < AMT; am++) {
                int row = wm * (AMT * 16) + am * 16 + r;
                a[am][0] = __float_as_uint(Ab[row][kb + cq]);
                a[am][1] = __float_as_uint(Ab[row + 8][kb + cq]);
                a[am][2] = __float_as_uint(Ab[row][kb + cq + 4]);
                a[am][3] = __float_as_uint(Ab[row + 8][kb + cq + 4]);
            }
            uint32_t b[4][2];
#pragma unroll
            for (int an = 0; an < 4; an++) {
                int nrow = wn * 32 + an * 8 + r;
                b[an][0] = __float_as_uint(Bb[nrow][kb + cq]);
                b[an][1] = __float_as_uint(Bb[nrow][kb + cq + 4]);
            }
#pragma unroll
            for (int am = 0; am < AMT; am++)
#pragma unroll
                for (int an = 0; an < 4; an++)
                    mma_tf32(acc[am][an], a[am], b[an]);
        }
        buf = (buf == 2) ? 0 : buf + 1;
    }

#pragma unroll
    for (int am = 0; am < AMT; am++) {
        int rw0 = m0 + wm * (AMT * 16) + am * 16 + r;
        int rw1 = rw0 + 8;
#pragma unroll
        for (int an = 0; an < 4; an++) {
            int col = n0 + wn * 32 + an * 8 + cq * 2;
            float add0 = 0.f, add1 = 0.f;
            if (bias) { add0 += bias[col]; add1 += bias[col + 1]; }
            if (rowv) { add0 += rowv[col]; add1 += rowv[col + 1]; }
            acc[am][an][0] += add0; acc[am][an][1] += add1;
            acc[am][an][2] += add0; acc[am][an][3] += add1;
            if (base) {
                if (rw0 < M) {
                    acc[am][an][0] += base[(size_t)rw0 * ldc + col];
                    acc[am][an][1] += base[(size_t)rw0 * ldc + col + 1];
                }
                if (rw1 < M) {
                    acc[am][an][2] += base[(size_t)rw1 * ldc + col];
                    acc[am][an][3] += base[(size_t)rw1 * ldc + col + 1];
                }
            }
        }
    }

    if (MODE == 0 || MODE == 1) {
#pragma unroll
        for (int am = 0; am < AMT; am++) {
            int rw0 = m0 + wm * (AMT * 16) + am * 16 + r;
            int rw1 = rw0 + 8;
#pragma unroll
            for (int an = 0; an < 4; an++) {
                int col = n0 + wn * 32 + an * 8 + cq * 2;
                if (rw0 < M) {
                    float v0 = acc[am][an][0], v1 = acc[am][an][1];
                    if (act) { v0 = fmaxf(v0, 0.f); v1 = fmaxf(v1, 0.f); }
                    if (roundOut) { v0 = tf32r(v0); v1 = tf32r(v1); }
                    C[(size_t)rw0 * ldc + col] = v0;
                    C[(size_t)rw0 * ldc + col + 1] = v1;
                }
                if (rw1 < M) {
                    float v2 = acc[am][an][2], v3 = acc[am][an][3];
                    if (act) { v2 = fmaxf(v2, 0.f); v3 = fmaxf(v3, 0.f); }
                    if (roundOut) { v2 = tf32r(v2); v3 = tf32r(v3); }
                    C[(size_t)rw1 * ldc + col] = v2;
                    C[(size_t)rw1 * ldc + col + 1] = v3;
                }
            }
        }
    }

    if (MODE >= 1) {
        float cold[16], cv[16], hv[16];
        size_t cBase = ((size_t)(blockIdx.y * gridDim.x + blockIdx.x) * 256 + tid) * 16;
        if (MODE == 2) {
#pragma unroll
            for (int j = 0; j < 4; j++)
                *(float4*)&cold[j * 4] = *(const float4*)&g_c[cBase + j * 4];
        } else {
#pragma unroll
            for (int j = 0; j < 16; j++) cold[j] = 0.f;
        }
#pragma unroll
        for (int am = 0; am < AMT; am++) {
#pragma unroll
            for (int hs = 0; hs < 2; hs++) {
#pragma unroll
                for (int e = 0; e < 2; e++) {
                    int q = hs * 2 + e;
                    int idx = am * 4 + hs * 2 + e;
                    float iv = sigf(acc[am][0][q]);
                    float fv = sigf(acc[am][1][q]);
                    float gv = tanhf(acc[am][2][q]);
                    float ov = sigf(acc[am][3][q]);
                    float cn = fv * cold[idx] + iv * gv;
                    cv[idx] = cn;
                    hv[idx] = ov * tanhf(cn);
                }
            }
        }
        if (!lastStep) {
#pragma unroll
            for (int j = 0; j < 4; j++)
                *(float4*)&g_c[cBase + j * 4] = *(float4*)&cv[j * 4];
        }
        float* sh = &As[0][0][0];
        __syncthreads();
#pragma unroll
        for (int am = 0; am < AMT; am++)
#pragma unroll
            for (int hs = 0; hs < 2; hs++)
#pragma unroll
                for (int e = 0; e < 2; e++) {
                    int row_l = wm * (AMT * 16) + am * 16 + r + hs * 8;
                    int ul = wn * 8 + cq * 2 + e;
                    sh[row_l * 33 + ul] = hv[am * 4 + hs * 2 + e];
                }
        __syncthreads();
        int row_l = tid >> 1, half = tid & 1;
        int ubase = n0 >> 2;
        size_t go = (size_t)(m0 + row_l) * DM + ubase + half * 16;
        const float* src = &sh[row_l * 33 + half * 16];
        if (!lastStep) {
#pragma unroll
            for (int j = 0; j < 4; j++) {
                float4 ev = *(const float4*)(g_enc + go + j * 4);
                float4 o;
                o.x = tf32r(ev.x + src[j * 4 + 0]);
                o.y = tf32r(ev.y + src[j * 4 + 1]);
                o.z = tf32r(ev.z + src[j * 4 + 2]);
                o.w = tf32r(ev.w + src[j * 4 + 3]);
                *(float4*)(hOut + go + j * 4) = o;
            }
        } else {
            const float* sg = g_supg + ubase + half * 16;
            float p = 0.f;
#pragma unroll
            for (int j = 0; j < 16; j++)
                p += (g_enc[go + j] + src[j]) * sg[j];
            p += __shfl_down_sync(0xffffffffu, p, 1);
            if (half == 0) atomicAdd(hOut + m0 + row_l, p);
        }
    }
}

// ------------------- residual layernorm -------------------
__global__ void __launch_bounds__(256)
ln_kernel(const float* __restrict__ g, const float* __restrict__ b) {
    __shared__ float s_red[16];
    int row = blockIdx.x, t = threadIdx.x;
    float v = g_enc[(size_t)row * DM + t] + g_vec[(size_t)row * DM + t];
    float s1 = warp_sum(v), s2 = warp_sum(v * v);
    if ((t & 31) == 0) { s_red[t >> 5] = s1; s_red[8 + (t >> 5)] = s2; }
    __syncthreads();
    float S1 = 0.f, S2 = 0.f;
#pragma unroll
    for (int i = 0; i < 8; i++) { S1 += s_red[i]; S2 += s_red[8 + i]; }
    float mean = S1 * (1.0f / 256.0f);
    float var = S2 * (1.0f / 256.0f) - mean * mean;
    g_enc[(size_t)row * DM + t] = tf32r((v - mean) * rsqrtf(var + 1e-5f) * g[t] + b[t]);
}

// rpart (supg computed in-block; block 0 publishes g_supg)
__global__ void rpart_kernel(const float* __restrict__ whh) {
    __shared__ float sg[DM];
    int t = threadIdx.x;
    float s = 0.f;
#pragma unroll
    for (int i = 0; i < NSUP; i++) s += g_enc[(size_t)(NB + i) * DM + t];
    s *= (1.0f / NSUP);
    sg[t] = s;
    if (blockIdx.x == 0) g_supg[t] = s;
    __syncthreads();
    int n = blockIdx.x * 256 + t;
    const float* row = whh + (size_t)permN(n) * LH + DM;
    float acc = 0.f;
    for (int k = 0; k < DM; k += 4) {
        float4 w = *(const float4*)(row + k);
        acc += w.x * sg[k] + w.y * sg[k + 1] + w.z * sg[k + 2] + w.w * sg[k + 3];
    }
    g_rpart[n] = acc;
}

// ------------------- host -------------------
extern "C" void kernel_launch(void* const* d_in, const int* in_sizes, int n_in,
                              void* d_out, int out_size) {
    const int* qry      = (const int*)d_in[0];
    const int* sup      = (const int*)d_in[1];
    const int* q_l1     = (const int*)d_in[2];
    const int* q_deg_l  = (const int*)d_in[3];
    const int* q_r1     = (const int*)d_in[4];
    const int* q_deg_r  = (const int*)d_in[5];
    const int* s_l1     = (const int*)d_in[6];
    const int* s_deg_l  = (const int*)d_in[7];
    const int* s_r1     = (const int*)d_in[8];
    const int* s_deg_r  = (const int*)d_in[9];
    const float* emb    = (const float*)d_in[10];
    const float* gcn_w_w = (const float*)d_in[11];
    const float* gcn_w_b = (const float*)d_in[12];
    const float* gcn_b   = (const float*)d_in[13];
    const float* g1_w    = (const float*)d_in[14];
    const float* g1_b    = (const float*)d_in[15];
    const float* ln1_g   = (const float*)d_in[16];
    const float* ln1_b   = (const float*)d_in[17];
    const float* g2_w    = (const float*)d_in[18];
    const float* g2_b    = (const float*)d_in[19];
    const float* gate_temp = (const float*)d_in[20];
    const float* se_p1_w = (const float*)d_in[21];
    const float* se_p1_b = (const float*)d_in[22];
    const float* se_p2_w = (const float*)d_in[23];
    const float* se_p2_b = (const float*)d_in[24];
    const float* se_ln_g = (const float*)d_in[25];
    const float* se_ln_b = (const float*)d_in[26];
    const float* w_ih    = (const float*)d_in[27];
    const float* w_hh    = (const float*)d_in[28];
    const float* b_ih    = (const float*)d_in[29];
    const float* b_hh    = (const float*)d_in[30];

    float *vec, *h1, *enc, *xpart, *hA, *hB, *bsum, *rpart;
    float *wihR, *whhR, *p1R, *p2R;
    cudaGetSymbolAddress((void**)&vec, g_vec);
    cudaGetSymbolAddress((void**)&h1, g_h1);
    cudaGetSymbolAddress((void**)&enc, g_enc);
    cudaGetSymbolAddress((void**)&xpart, g_xpart);
    cudaGetSymbolAddress((void**)&hA, g_h);
    cudaGetSymbolAddress((void**)&hB, g_hB);
    cudaGetSymbolAddress((void**)&bsum, g_bsum);
    cudaGetSymbolAddress((void**)&rpart, g_rpart);
    cudaGetSymbolAddress((void**)&wihR, g_wihR);
    cudaGetSymbolAddress((void**)&whhR, g_whhR);
    cudaGetSymbolAddress((void**)&p1R, g_p1R);
    cudaGetSymbolAddress((void**)&p2R, g_p2R);

    // 0: topk, 1: merged prep, 2: zero out, 3: projgather (profiled)
    topk_kernel<<<NUNITS, 128>>>(
        qry, sup, q_l1, q_deg_l, q_r1, q_deg_r, s_l1, s_deg_l, s_r1, s_deg_r, emb);
    prep_kernel<<<PREP_P2, 256>>>(gcn_w_w, b_ih, b_hh, w_ih, w_hh, se_p1_w, se_p2_w);
    zeroout_kernel<<<NB / 256, 256>>>((float*)d_out);
    projgather_kernel<<<PTILES, 256>>>(emb, gcn_w_b, gcn_b);
    agg_gate_kernel<<<(NUNITS + AW * AUPW - 1) / (AW * AUPW), 256>>>(
        qry, sup, q_l1, q_deg_l, q_r1, q_deg_r, s_l1, s_deg_l, s_r1, s_deg_r,
        emb, g1_w, g1_b, ln1_g, ln1_b, g2_w, g2_b, gate_temp);

    // support encoder
    gemm_v3<64, 0><<<dim3(DI / 128, (NROWS + 63) / 64), 256>>>(
        vec, DM, p1R, DM, se_p1_b, nullptr, nullptr, h1, DI, NROWS, DI, DM, 1, 1, nullptr, 0);
    gemm_v3<64, 0><<<dim3(DM / 128, (NROWS + 63) / 64), 256>>>(
        h1, DI, p2R, DI, se_p2_b, nullptr, nullptr, enc, DM, NROWS, DM, DI, 0, 0, nullptr, 0);
    ln_kernel<<<NROWS, 256>>>(se_ln_g, se_ln_b);

    rpart_kernel<<<GR / 256, 256>>>(w_hh);

    // step 1: xpart GEMM + fused cell (c=0) -> hA
    gemm_v3<128, 1><<<dim3(GR / 128, NB / 128), 256>>>(
        enc, DM, wihR, DM, bsum, nullptr, nullptr, xpart, GR, NB, GR, DM, 0, 0, hA, 0);

    // steps 2..4: gates GEMM + fused cell; last step fuses final dot into d_out
    float* hin = hA; float* hout = hB;
    for (int s = 0; s < 3; s++) {
        int last = (s == 2);
        gemm_v3<128, 2><<<dim3(GR / 128, NB / 128), 256>>>(
            hin, DM, whhR, DM, nullptr, xpart, rpart, xpart, GR, NB, GR, DM, 0, 0,
            last ? (float*)d_out : hout, last);
        float* t = hin; hin = hout; hout = t;
    }
}

// round 15
// speedup vs baseline: 1.0174x; 1.0174x over previous
#include <cuda_runtime.h>
#include <cstdint>
#include <math.h>

#define NB 4096
#define NSUP 5
#define NROWS (NB + NSUP)
#define ED 128
#define DM 256
#define DI 512
#define LH 512
#define GR 1024
#define PADI 200000
#define MAXK 64
#define TOPK 10
#define NUNITS (2 * NB + 2 * NSUP)   // 8202
#define PROWS (NUNITS * TOPK)        // 82020
#define PROWS_PAD 82080
#define PTILES ((PROWS + 127) / 128) // 641
#define KPAD 36

// ------------------- device scratch -------------------
__device__ float g_vec[NROWS * DM];
__device__ float g_h1[NROWS * DI];
__device__ float g_enc[NROWS * DM];
__device__ float g_supg[DM];
__device__ float g_rpart[GR];
__device__ float g_bsum[GR];
__device__ float g_xpart[(size_t)NB * GR];
__device__ float g_h[(size_t)NB * DM];
__device__ float g_hB[(size_t)NB * DM];
__device__ float g_c[(size_t)NB * DM];
__device__ float g_wihR[GR * DM];
__device__ float g_whhR[GR * DM];
__device__ float g_p1R[DI * DM];
__device__ float g_p2R[DM * DI];
__device__ float g_gcnR[ED * DM];
__device__ int   g_rowids[PROWS_PAD * 2];
__device__ int4  g_uinfo[8208];
__device__ float g_proj[(size_t)(PTILES * 128) * ED];

__device__ __forceinline__ float warp_sum(float v) {
#pragma unroll
    for (int o = 16; o; o >>= 1) v += __shfl_xor_sync(0xffffffffu, v, o);
    return v;
}
__device__ __forceinline__ float sigf(float x) { return 1.0f / (1.0f + expf(-x)); }
__device__ __forceinline__ float tf32r(float v) {
    uint32_t r;
    asm("cvt.rna.tf32.f32 %0, %1;" : "=r"(r) : "f"(v));
    return __uint_as_float(r);
}
__device__ __forceinline__ float4 tf32r4(float4 v) {
    v.x = tf32r(v.x); v.y = tf32r(v.y); v.z = tf32r(v.z); v.w = tf32r(v.w);
    return v;
}
__device__ __forceinline__ void mma_tf32(float* c, const uint32_t* a, const uint32_t* b) {
    asm volatile(
        "mma.sync.aligned.m16n8k8.row.col.f32.tf32.tf32.f32 "
        "{%0,%1,%2,%3}, {%4,%5,%6,%7}, {%8,%9}, {%0,%1,%2,%3};"
        : "+f"(c[0]), "+f"(c[1]), "+f"(c[2]), "+f"(c[3])
        : "r"(a[0]), "r"(a[1]), "r"(a[2]), "r"(a[3]), "r"(b[0]), "r"(b[1]));
}
__device__ __forceinline__ void cp_async16(uint32_t s, const void* g, int sz) {
    asm volatile("cp.async.cg.shared.global [%0], [%1], 16, %2;\n"
                 :: "r"(s), "l"(g), "r"(sz));
}
__device__ __forceinline__ void cp_commit() { asm volatile("cp.async.commit_group;\n"); }
__device__ __forceinline__ void cp_wait1() { asm volatile("cp.async.wait_group 1;\n"); }
__device__ __forceinline__ void cp_wait0() { asm volatile("cp.async.wait_group 0;\n"); }

__device__ __forceinline__ int permN(int n) {
    return (((n >> 3) & 3) << 9) + ((n >> 5) << 3) + (n & 7);
}

__device__ __forceinline__ void unit_decode(
    int ur,
    const int* qry, const int* sup,
    const int* q_l1, const int* q_deg_l, const int* q_r1, const int* q_deg_r,
    const int* s_l1, const int* s_deg_l, const int* s_r1, const int* s_deg_r,
    const int** conn, int* deg, int* selfid, size_t* outoff) {
    if (ur < NB) {
        *conn = q_l1 + ur * MAXK * 2; *deg = q_deg_l[ur];
        *selfid = qry[ur * 2 + 0]; *outoff = (size_t)ur * DM;
    } else if (ur < 2 * NB) {
        int b = ur - NB;
        *conn = q_r1 + b * MAXK * 2; *deg = q_deg_r[b];
        *selfid = qry[b * 2 + 1]; *outoff = (size_t)b * DM + ED;
    } else if (ur < 2 * NB + NSUP) {
        int i = ur - 2 * NB;
        *conn = s_l1 + i * MAXK * 2; *deg = s_deg_l[i];
        *selfid = sup[i * 2 + 0]; *outoff = (size_t)(NB + i) * DM;
    } else {
        int i = ur - 2 * NB - NSUP;
        *conn = s_r1 + i * MAXK * 2; *deg = s_deg_r[i];
        *selfid = sup[i * 2 + 1]; *outoff = (size_t)(NB + i) * DM + ED;
    }
}

// ------------------- prep kernels (R12 structure, float4-vectorized rounds) -------------------
__global__ void prep_kernel(const float* __restrict__ gcn,
                            const float* __restrict__ b_ih,
                            const float* __restrict__ b_hh,
                            float* __restrict__ out) {
    int t = threadIdx.x, b = blockIdx.x;
    if (b < 128) {
        int i = b * 256 + t;
        g_gcnR[i] = tf32r(gcn[i]);
    } else if (b < 132) {
        int n = (b - 128) * 256 + t;
        int p = permN(n);
        g_bsum[n] = b_ih[p] + b_hh[p];
    } else if (b == 132) {
        if (t < (PROWS_PAD - PROWS) * 2) g_rowids[PROWS * 2 + t] = 0;
    } else {
        int i = (b - 133) * 256 + t;
        if (i < NB) out[i] = 0.f;
    }
}
// wih/whh permute+round, float4: block = 4 rows, thread t -> row 4*(b)+(t>>6), qs=(t&63)
__global__ void roundA_kernel(const float* __restrict__ w_ih, const float* __restrict__ w_hh) {
    int t = threadIdx.x, b = blockIdx.x;
    int n = (b & 255) * 4 + (t >> 6);
    int q = t & 63;
    int p = permN(n);
    if (b < 256) {
        float4 v = ((const float4*)(w_ih + p * DM))[q];
        ((float4*)(g_wihR + n * DM))[q] = tf32r4(v);
    } else {
        float4 v = ((const float4*)(w_hh + (size_t)p * LH))[q];
        ((float4*)(g_whhR + n * DM))[q] = tf32r4(v);
    }
}
__global__ void roundB_kernel(const float* __restrict__ p1, const float* __restrict__ p2) {
    int i = blockIdx.x * 256 + threadIdx.x;
    if (i < DI * DM / 4) {
        ((float4*)g_p1R)[i] = tf32r4(((const float4*)p1)[i]);
    } else {
        int j = i - DI * DM / 4;
        ((float4*)g_p2R)[j] = tf32r4(((const float4*)p2)[j]);
    }
}

// ------------------- phase 1: sims + top-10 -------------------
__global__ void __launch_bounds__(128)
topk_kernel(const int* __restrict__ qry, const int* __restrict__ sup,
            const int* __restrict__ q_l1, const int* __restrict__ q_deg_l,
            const int* __restrict__ q_r1, const int* __restrict__ q_deg_r,
            const int* __restrict__ s_l1, const int* __restrict__ s_deg_l,
            const int* __restrict__ s_r1, const int* __restrict__ s_deg_r,
            const float* __restrict__ emb) {
    __shared__ float s_selfn[ED];
    __shared__ float s_sim[MAXK];
    __shared__ int s_rel[MAXK], s_ent[MAXK];
    __shared__ float s_red[4];
    __shared__ float s_sc[1];

    int unit = blockIdx.x, tid = threadIdx.x;
    int lane = tid & 31, warp = tid >> 5;

    const int* conn; int deg, selfid; size_t outoff;
    unit_decode(unit, qry, sup, q_l1, q_deg_l, q_r1, q_deg_r,
                s_l1, s_deg_l, s_r1, s_deg_r, &conn, &deg, &selfid, &outoff);

    float se = emb[(size_t)selfid * ED + tid];
    float ss = warp_sum(se * se);
    if (lane == 0) s_red[warp] = ss;
    __syncthreads();
    if (tid == 0)
        s_sc[0] = 1.0f / fmaxf(sqrtf(s_red[0] + s_red[1] + s_red[2] + s_red[3]), 1e-12f);
    __syncthreads();
    s_selfn[tid] = se * s_sc[0];
    __syncthreads();

    int gid = lane >> 3, gl = lane & 7;
    float4 sn[4];
#pragma unroll
    for (int q = 0; q < 4; q++) sn[q] = ((const float4*)s_selfn)[gl + 8 * q];

#pragma unroll
    for (int jt = 0; jt < 4; jt++) {
        int j = warp * 16 + jt * 4 + gid;
        int2 ids = ((const int2*)conn)[j];
        const float4* er = (const float4*)(emb + (size_t)ids.y * ED);
        float dot = 0.f, sq = 0.f;
#pragma unroll
        for (int q = 0; q < 4; q++) {
            float4 e = er[gl + 8 * q];
            dot += e.x * sn[q].x + e.y * sn[q].y + e.z * sn[q].z + e.w * sn[q].w;
            sq += e.x * e.x + e.y * e.y + e.z * e.z + e.w * e.w;
        }
#pragma unroll
        for (int o = 4; o; o >>= 1) {
            unsigned long long v =
                ((unsigned long long)__float_as_uint(sq) << 32) | __float_as_uint(dot);
            unsigned long long w = __shfl_xor_sync(0xffffffffu, v, o);
            dot += __uint_as_float((uint32_t)w);
            sq += __uint_as_float((uint32_t)(w >> 32));
        }
        if (gl == 0) {
            float sim = dot / fmaxf(sqrtf(sq), 1e-12f);
            if (ids.x == PADI) sim -= 1e9f;
            s_sim[j] = sim; s_rel[j] = ids.x; s_ent[j] = ids.y;
        }
    }
    __syncthreads();

    if (warp == 0) {
        float v0 = s_sim[lane], v1 = s_sim[lane + 32];
        int nv = 0, mask = 0;
#pragma unroll
        for (int t = 0; t < TOPK; t++) {
            float mv = v0; int mi = lane;
            if (v1 > mv) { mv = v1; mi = lane + 32; }
#pragma unroll
            for (int o = 16; o; o >>= 1) {
                float ov = __shfl_xor_sync(0xffffffffu, mv, o);
                int oi = __shfl_xor_sync(0xffffffffu, mi, o);
                if (ov > mv || (ov == mv && oi < mi)) { mv = ov; mi = oi; }
            }
            if (lane == 0) {
                int rel = s_rel[mi], ent = s_ent[mi];
                g_rowids[(unit * TOPK + t) * 2 + 0] = rel;
                g_rowids[(unit * TOPK + t) * 2 + 1] = ent;
                if (rel == PADI) mask |= (1 << t); else nv++;
            }
            if (mi == lane) v0 = -3.0e38f;
            if (mi == lane + 32) v1 = -3.0e38f;
        }
        if (lane == 0) g_uinfo[unit] = make_int4(selfid, deg, nv, mask);
    }
}

// ------------------- phase 2: gathered proj GEMM (R12 pipeline) -------------------
__global__ void __launch_bounds__(256, 2)
projgather_kernel(const float* __restrict__ emb,
                  const float* __restrict__ gcn_w_b,
                  const float* __restrict__ gcn_b) {
    __shared__ float As[3][128][KPAD];
    __shared__ float Bs[3][128][KPAD];
    __shared__ int2 s_ids[128];

    int tid = threadIdx.x;
    int m0 = blockIdx.x << 7;
    int lane = tid & 31, warp = tid >> 5;
    int wm = warp >> 2, wn = warp & 3;
    int r = lane >> 2, cq = lane & 3;

    uint32_t sA = (uint32_t)__cvta_generic_to_shared(&As[0][0][0]);
    uint32_t sB = (uint32_t)__cvta_generic_to_shared(&Bs[0][0][0]);
    const uint32_t strAB = 128 * KPAD * 4;

    if (tid < 128) s_ids[tid] = ((const int2*)g_rowids)[m0 + tid];
    __syncthreads();

    float acc[4][4][4];
#pragma unroll
    for (int i = 0; i < 4; i++)
#pragma unroll
        for (int j = 0; j < 4; j++)
#pragma unroll
            for (int q = 0; q < 4; q++) acc[i][j][q] = 0.f;

    auto stage = [&](int buf, int k0) {
        bool lo = (k0 < ED);
#pragma unroll
        for (int i = 0; i < 4; i++) {
            int seg = tid + i * 256;
            int row = seg >> 3, k4 = (seg & 7) << 2;
            int2 ids = s_ids[row];
            const float* srcA = emb + (size_t)(lo ? ids.x : ids.y) * ED
                                + (lo ? k0 : k0 - ED) + k4;
            cp_async16(sA + buf * strAB + (row * KPAD + k4) * 4, srcA, 16);
            cp_async16(sB + buf * strAB + (row * KPAD + k4) * 4,
                       g_gcnR + row * DM + k0 + k4, 16);
        }
        cp_commit();
    };

    stage(0, 0);
    stage(1, 32);
    int buf = 0;
    for (int kt = 0; kt < 8; kt++) {
        if (kt == 7) cp_wait0(); else cp_wait1();
        __syncthreads();

        const float (*Ab)[KPAD] = As[buf];
        const float (*Bb)[KPAD] = Bs[buf];
#pragma unroll
        for (int ks = 0; ks < 4; ks++) {
            int kb = ks * 8;
            uint32_t a[4][4];
#pragma unroll
            for (int am = 0; am < 4; am++) {
                int row = wm * 64 + am * 16 + r;
                a[am][0] = __float_as_uint(Ab[row][kb + cq]);
                a[am][1] = __float_as_uint(Ab[row + 8][kb + cq]);
                a[am][2] = __float_as_uint(Ab[row][kb + cq + 4]);
                a[am][3] = __float_as_uint(Ab[row + 8][kb + cq + 4]);
            }
            uint32_t b[4][2];
#pragma unroll
            for (int an = 0; an < 4; an++) {
                int nrow = wn * 32 + an * 8 + r;
                b[an][0] = __float_as_uint(Bb[nrow][kb + cq]);
                b[an][1] = __float_as_uint(Bb[nrow][kb + cq + 4]);
            }
#pragma unroll
            for (int am = 0; am < 4; am++)
#pragma unroll
                for (int an = 0; an < 4; an++)
                    mma_tf32(acc[am][an], a[am], b[an]);
        }
        if (kt + 2 < 8) stage(buf + 2 >= 3 ? buf - 1 : buf + 2, (kt + 2) << 5);
        buf = (buf == 2) ? 0 : buf + 1;
    }

#pragma unroll
    for (int am = 0; am < 4; am++) {
        int rw0 = m0 + wm * 64 + am * 16 + r;
        int rw1 = rw0 + 8;
#pragma unroll
        for (int an = 0; an < 4; an++) {
            int col = wn * 32 + an * 8 + cq * 2;
            float b0 = gcn_w_b[col] + gcn_b[col];
            float b1 = gcn_w_b[col + 1] + gcn_b[col + 1];
            if (rw0 < PROWS) {
                float v0 = acc[am][an][0] + b0;
                float v1 = acc[am][an][1] + b1;
                v0 = v0 > 0.f ? v0 : 0.01f * v0;
                v1 = v1 > 0.f ? v1 : 0.01f * v1;
                g_proj[(size_t)rw0 * ED + col] = v0;
                g_proj[(size_t)rw0 * ED + col + 1] = v1;
            }
            if (rw1 < PROWS) {
                float v2 = acc[am][an][2] + b0;
                float v3 = acc[am][an][3] + b1;
                v2 = v2 > 0.f ? v2 : 0.01f * v2;
                v3 = v3 > 0.f ? v3 : 0.01f * v3;
                g_proj[(size_t)rw1 * ED + col] = v2;
                g_proj[(size_t)rw1 * ED + col + 1] = v3;
            }
        }
    }
}

// ------------------- phase 3: warp-per-unit agg + gate MLP + output -------------------
#define AW 8
#define AUPW 4
__global__ void __launch_bounds__(256)
agg_gate_kernel(const int* __restrict__ qry, const int* __restrict__ sup,
                const int* __restrict__ q_l1, const int* __restrict__ q_deg_l,
                const int* __restrict__ q_r1, const int* __restrict__ q_deg_r,
                const int* __restrict__ s_l1, const int* __restrict__ s_deg_l,
                const int* __restrict__ s_r1, const int* __restrict__ s_deg_r,
                const float* __restrict__ emb,
                const float* __restrict__ g1_w, const float* __restrict__ g1_b,
                const float* __restrict__ ln1_g, const float* __restrict__ ln1_b,
                const float* __restrict__ g2_w, const float* __restrict__ g2_b,
                const float* __restrict__ gate_temp) {
    __shared__ float4 s_g1[64 * 32];
    __shared__ float4 s_agg[AW][33];
    __shared__ float s_b[64], s_lg[64], s_lb[64], s_g2[64];
    __shared__ float s_scal[2];

    int tid = threadIdx.x;
    int lane = tid & 31, warp = tid >> 5;

#pragma unroll
    for (int i = 0; i < 8; i++) {
        int f = tid + i * 256;
        int d = f >> 5, g = f & 31;
        s_g1[d * 32 + (g ^ (d & 7))] = ((const float4*)g1_w)[f];
    }
    if (tid < 64) {
        s_b[tid] = g1_b[tid]; s_lg[tid] = ln1_g[tid];
        s_lb[tid] = ln1_b[tid]; s_g2[tid] = g2_w[tid];
    }
    if (tid == 0) {
        s_scal[0] = g2_b[0];
        s_scal[1] = 1.0f / fminf(fmaxf(gate_temp[0], 0.1f), 5.0f);
    }
    __syncthreads();

    float g2b = s_scal[0], invT = s_scal[1];

    for (int u = 0; u < AUPW; u++) {
        int unit = (blockIdx.x * AW + warp) * AUPW + u;
        if (unit >= NUNITS) break;
        int4 info = g_uinfo[unit];

        const float4* pr = (const float4*)(g_proj + (size_t)unit * TOPK * ED);
        float4 a = make_float4(0.f, 0.f, 0.f, 0.f);
#pragma unroll
        for (int j = 0; j < TOPK; j++) {
            if (!((info.w >> j) & 1)) {
                float4 p = pr[j * 32 + lane];
                a.x += p.x; a.y += p.y; a.z += p.z; a.w += p.w;
            }
        }
        float inv = 1.0f / fmaxf((float)info.z, 1.0f);
        a.x *= inv; a.y *= inv; a.z *= inv; a.w *= inv;
        s_agg[warp][lane] = a;
        __syncwarp();

        float y0 = s_b[lane], y1 = s_b[lane + 32];
        int sw = lane & 7;
        const float4* w0 = &s_g1[lane * 32];
        const float4* w1 = &s_g1[(lane + 32) * 32];
#pragma unroll
        for (int k = 0; k < 32; k++) {
            float4 av = s_agg[warp][k];
            float4 a0 = w0[k ^ sw];
            float4 a1 = w1[k ^ sw];
            y0 += av.x * a0.x + av.y * a0.y + av.z * a0.z + av.w * a0.w;
            y1 += av.x * a1.x + av.y * a1.y + av.z * a1.z + av.w * a1.w;
        }

        float s1 = warp_sum(y0 + y1);
        float s2 = warp_sum(y0 * y0 + y1 * y1);
        float mean = s1 * (1.0f / 64.0f);
        float var = s2 * (1.0f / 64.0f) - mean * mean;
        float rstd = rsqrtf(var + 1e-5f);
        float hv0 = fmaxf((y0 - mean) * rstd * s_lg[lane] + s_lb[lane], 0.f);
        float hv1 = fmaxf((y1 - mean) * rstd * s_lg[lane + 32] + s_lb[lane + 32], 0.f);
        float logit = warp_sum(hv0 * s_g2[lane] + hv1 * s_g2[lane + 32]) + g2b;
        float gate = 1.0f / (1.0f + expf(-logit * invT));
        if (info.y <= 0) gate = 0.f;

        const int* conn; int deg, selfid; size_t outoff;
        unit_decode(unit, qry, sup, q_l1, q_deg_l, q_r1, q_deg_r,
                    s_l1, s_deg_l, s_r1, s_deg_r, &conn, &deg, &selfid, &outoff);
        float4 e = ((const float4*)(emb + (size_t)info.x * ED))[lane];
        float4 o;
        o.x = tf32r(tanhf(e.x + gate * a.x));
        o.y = tf32r(tanhf(e.y + gate * a.y));
        o.z = tf32r(tanhf(e.z + gate * a.z));
        o.w = tf32r(tanhf(e.w + gate * a.w));
        *(float4*)(g_vec + outoff + lane * 4) = o;
        __syncwarp();
    }
}

// ------------------- TF32 GEMM (R12 pipeline) + fused LSTM cell -------------------
template<int BMT, int MODE>
__global__ void __launch_bounds__(256, 2)
gemm_v3(const float* __restrict__ A, int lda,
        const float* __restrict__ W, int ldw,
        const float* __restrict__ bias,
        const float* __restrict__ base,
        const float* __restrict__ rowv,
        float* __restrict__ C, int ldc,
        int M, int N, int K, int act, int roundOut,
        float* __restrict__ hOut, int lastStep) {
    constexpr int AMT = BMT / 32;
    constexpr int ASEG = BMT * 8 / 256;
    __shared__ float As[3][BMT][KPAD];
    __shared__ float Bs[3][128][KPAD];

    int tid = threadIdx.x;
    int m0 = blockIdx.y * BMT, n0 = blockIdx.x << 7;
    int lane = tid & 31, warp = tid >> 5;
    int wm = warp >> 2, wn = warp & 3;
    int r = lane >> 2, cq = lane & 3;

    uint32_t sA = (uint32_t)__cvta_generic_to_shared(&As[0][0][0]);
    uint32_t sB = (uint32_t)__cvta_generic_to_shared(&Bs[0][0][0]);
    const uint32_t strA = BMT * KPAD * 4;
    const uint32_t strB = 128 * KPAD * 4;

    float acc[AMT][4][4];
#pragma unroll
    for (int i = 0; i < AMT; i++)
#pragma unroll
        for (int j = 0; j < 4; j++)
#pragma unroll
            for (int q = 0; q < 4; q++) acc[i][j][q] = 0.f;

    int KT = K >> 5;

    auto stage = [&](int buf, int k0) {
#pragma unroll
        for (int i = 0; i < ASEG; i++) {
            int seg = tid + i * 256;
            int row = seg >> 3, k4 = (seg & 7) << 2;
            int m = m0 + row;
            cp_async16(sA + buf * strA + (row * KPAD + k4) * 4,
                       A + (size_t)m * lda + k0 + k4, m < M ? 16 : 0);
        }
#pragma unroll
        for (int i = 0; i < 4; i++) {
            int seg = tid + i * 256;
            int row = seg >> 3, k4 = (seg & 7) << 2;
            cp_async16(sB + buf * strB + (row * KPAD + k4) * 4,
                       W + (size_t)(n0 + row) * ldw + k0 + k4, 16);
        }
        cp_commit();
    };

    stage(0, 0);
    stage(1, 32);
    int buf = 0;
    for (int kt = 0; kt < KT; kt++) {
        if (kt == KT - 1) cp_wait0(); else cp_wait1();
        __syncthreads();

        const float (*Ab)[KPAD] = As[buf];
        const float (*Bb)[KPAD] = Bs[buf];
#pragma unroll
        for (int ks = 0; ks < 4; ks++) {
            int kb = ks * 8;
            uint32_t a[AMT][4];
#pragma unroll
            for (int am = 0; am < AMT; am++) {
                int row = wm * (AMT * 16) + am * 16 + r;
                a[am][0] = __float_as_uint(Ab[row][kb + cq]);
                a[am][1] = __float_as_uint(Ab[row + 8][kb + cq]);
                a[am][2] = __float_as_uint(Ab[row][kb + cq + 4]);
                a[am][3] = __float_as_uint(Ab[row + 8][kb + cq + 4]);
            }
            uint32_t b[4][2];
#pragma unroll
            for (int an = 0; an < 4; an++) {
                int nrow = wn * 32 + an * 8 + r;
                b[an][0] = __float_as_uint(Bb[nrow][kb + cq]);
                b[an][1] = __float_as_uint(Bb[nrow][kb + cq + 4]);
            }
#pragma unroll
            for (int am = 0; am < AMT; am++)
#pragma unroll
                for (int an = 0; an < 4; an++)
                    mma_tf32(acc[am][an], a[am], b[an]);
        }
        if (kt + 2 < KT) stage(buf + 2 >= 3 ? buf - 1 : buf + 2, (kt + 2) << 5);
        buf = (buf == 2) ? 0 : buf + 1;
    }

#pragma unroll
    for (int am = 0; am < AMT; am++) {
        int rw0 = m0 + wm * (AMT * 16) + am * 16 + r;
        int rw1 = rw0 + 8;
#pragma unroll
        for (int an = 0; an < 4; an++) {
            int col = n0 + wn * 32 + an * 8 + cq * 2;
            float add0 = 0.f, add1 = 0.f;
            if (bias) { add0 += bias[col]; add1 += bias[col + 1]; }
            if (rowv) { add0 += rowv[col]; add1 += rowv[col + 1]; }
            acc[am][an][0] += add0; acc[am][an][1] += add1;
            acc[am][an][2] += add0; acc[am][an][3] += add1;
            if (base) {
                if (rw0 < M) {
                    acc[am][an][0] += base[(size_t)rw0 * ldc + col];
                    acc[am][an][1] += base[(size_t)rw0 * ldc + col + 1];
                }
                if (rw1 < M) {
                    acc[am][an][2] += base[(size_t)rw1 * ldc + col];
                    acc[am][an][3] += base[(size_t)rw1 * ldc + col + 1];
                }
            }
        }
    }

    if (MODE == 0 || MODE == 1) {
#pragma unroll
        for (int am = 0; am < AMT; am++) {
            int rw0 = m0 + wm * (AMT * 16) + am * 16 + r;
            int rw1 = rw0 + 8;
#pragma unroll
            for (int an = 0; an < 4; an++) {
                int col = n0 + wn * 32 + an * 8 + cq * 2;
                if (rw0 < M) {
                    float v0 = acc[am][an][0], v1 = acc[am][an][1];
                    if (act) { v0 = fmaxf(v0, 0.f); v1 = fmaxf(v1, 0.f); }
                    if (roundOut) { v0 = tf32r(v0); v1 = tf32r(v1); }
                    C[(size_t)rw0 * ldc + col] = v0;
                    C[(size_t)rw0 * ldc + col + 1] = v1;
                }
                if (rw1 < M) {
                    float v2 = acc[am][an][2], v3 = acc[am][an][3];
                    if (act) { v2 = fmaxf(v2, 0.f); v3 = fmaxf(v3, 0.f); }
                    if (roundOut) { v2 = tf32r(v2); v3 = tf32r(v3); }
                    C[(size_t)rw1 * ldc + col] = v2;
                    C[(size_t)rw1 * ldc + col + 1] = v3;
                }
            }
        }
    }

    if (MODE >= 1) {
        float cold[16], cv[16], hv[16];
        size_t cBase = ((size_t)(blockIdx.y * gridDim.x + blockIdx.x) * 256 + tid) * 16;
        if (MODE == 2) {
#pragma unroll
            for (int j = 0; j < 4; j++)
                *(float4*)&cold[j * 4] = *(const float4*)&g_c[cBase + j * 4];
        } else {
#pragma unroll
            for (int j = 0; j < 16; j++) cold[j] = 0.f;
        }
#pragma unroll
        for (int am = 0; am < AMT; am++) {
#pragma unroll
            for (int hs = 0; hs < 2; hs++) {
#pragma unroll
                for (int e = 0; e < 2; e++) {
                    int q = hs * 2 + e;
                    int idx = am * 4 + hs * 2 + e;
                    float iv = sigf(acc[am][0][q]);
                    float fv = sigf(acc[am][1][q]);
                    float gv = tanhf(acc[am][2][q]);
                    float ov = sigf(acc[am][3][q]);
                    float cn = fv * cold[idx] + iv * gv;
                    cv[idx] = cn;
                    hv[idx] = ov * tanhf(cn);
                }
            }
        }
        if (!lastStep) {
#pragma unroll
            for (int j = 0; j < 4; j++)
                *(float4*)&g_c[cBase + j * 4] = *(float4*)&cv[j * 4];
        }
        float* sh = &As[0][0][0];
        __syncthreads();
#pragma unroll
        for (int am = 0; am < AMT; am++)
#pragma unroll
            for (int hs = 0; hs < 2; hs++)
#pragma unroll
                for (int e = 0; e < 2; e++) {
                    int row_l = wm * (AMT * 16) + am * 16 + r + hs * 8;
                    int ul = wn * 8 + cq * 2 + e;
                    sh[row_l * 33 + ul] = hv[am * 4 + hs * 2 + e];
                }
        __syncthreads();
        int row_l = tid >> 1, half = tid & 1;
        int ubase = n0 >> 2;
        size_t go = (size_t)(m0 + row_l) * DM + ubase + half * 16;
        const float* src = &sh[row_l * 33 + half * 16];
        if (!lastStep) {
#pragma unroll
            for (int j = 0; j < 4; j++) {
                float4 ev = *(const float4*)(g_enc + go + j * 4);
                float4 o;
                o.x = tf32r(ev.x + src[j * 4 + 0]);
                o.y = tf32r(ev.y + src[j * 4 + 1]);
                o.z = tf32r(ev.z + src[j * 4 + 2]);
                o.w = tf32r(ev.w + src[j * 4 + 3]);
                *(float4*)(hOut + go + j * 4) = o;
            }
        } else {
            const float* sg = g_supg + ubase + half * 16;
            float p = 0.f;
#pragma unroll
            for (int j = 0; j < 16; j++)
                p += (g_enc[go + j] + src[j]) * sg[j];
            p += __shfl_down_sync(0xffffffffu, p, 1);
            if (half == 0) atomicAdd(hOut + m0 + row_l, p);
        }
    }
}

// ------------------- residual layernorm -------------------
__global__ void __launch_bounds__(256)
ln_kernel(const float* __restrict__ g, const float* __restrict__ b) {
    __shared__ float s_red[16];
    int row = blockIdx.x, t = threadIdx.x;
    float v = g_enc[(size_t)row * DM + t] + g_vec[(size_t)row * DM + t];
    float s1 = warp_sum(v), s2 = warp_sum(v * v);
    if ((t & 31) == 0) { s_red[t >> 5] = s1; s_red[8 + (t >> 5)] = s2; }
    __syncthreads();
    float S1 = 0.f, S2 = 0.f;
#pragma unroll
    for (int i = 0; i < 8; i++) { S1 += s_red[i]; S2 += s_red[8 + i]; }
    float mean = S1 * (1.0f / 256.0f);
    float var = S2 * (1.0f / 256.0f) - mean * mean;
    g_enc[(size_t)row * DM + t] = tf32r((v - mean) * rsqrtf(var + 1e-5f) * g[t] + b[t]);
}

// rpart (supg computed in-block; block 0 publishes g_supg)
__global__ void rpart_kernel(const float* __restrict__ whh) {
    __shared__ float sg[DM];
    int t = threadIdx.x;
    float s = 0.f;
#pragma unroll
    for (int i = 0; i < NSUP; i++) s += g_enc[(size_t)(NB + i) * DM + t];
    s *= (1.0f / NSUP);
    sg[t] = s;
    if (blockIdx.x == 0) g_supg[t] = s;
    __syncthreads();
    int n = blockIdx.x * 256 + t;
    const float* row = whh + (size_t)permN(n) * LH + DM;
    float acc = 0.f;
    for (int k = 0; k < DM; k += 4) {
        float4 w = *(const float4*)(row + k);
        acc += w.x * sg[k] + w.y * sg[k + 1] + w.z * sg[k + 2] + w.w * sg[k + 3];
    }
    g_rpart[n] = acc;
}

// ------------------- host -------------------
extern "C" void kernel_launch(void* const* d_in, const int* in_sizes, int n_in,
                              void* d_out, int out_size) {
    const int* qry      = (const int*)d_in[0];
    const int* sup      = (const int*)d_in[1];
    const int* q_l1     = (const int*)d_in[2];
    const int* q_deg_l  = (const int*)d_in[3];
    const int* q_r1     = (const int*)d_in[4];
    const int* q_deg_r  = (const int*)d_in[5];
    const int* s_l1     = (const int*)d_in[6];
    const int* s_deg_l  = (const int*)d_in[7];
    const int* s_r1     = (const int*)d_in[8];
    const int* s_deg_r  = (const int*)d_in[9];
    const float* emb    = (const float*)d_in[10];
    const float* gcn_w_w = (const float*)d_in[11];
    const float* gcn_w_b = (const float*)d_in[12];
    const float* gcn_b   = (const float*)d_in[13];
    const float* g1_w    = (const float*)d_in[14];
    const float* g1_b    = (const float*)d_in[15];
    const float* ln1_g   = (const float*)d_in[16];
    const float* ln1_b   = (const float*)d_in[17];
    const float* g2_w    = (const float*)d_in[18];
    const float* g2_b    = (const float*)d_in[19];
    const float* gate_temp = (const float*)d_in[20];
    const float* se_p1_w = (const float*)d_in[21];
    const float* se_p1_b = (const float*)d_in[22];
    const float* se_p2_w = (const float*)d_in[23];
    const float* se_p2_b = (const float*)d_in[24];
    const float* se_ln_g = (const float*)d_in[25];
    const float* se_ln_b = (const float*)d_in[26];
    const float* w_ih    = (const float*)d_in[27];
    const float* w_hh    = (const float*)d_in[28];
    const float* b_ih    = (const float*)d_in[29];
    const float* b_hh    = (const float*)d_in[30];

    float *vec, *h1, *enc, *xpart, *hA, *hB, *bsum, *rpart;
    float *wihR, *whhR, *p1R, *p2R;
    cudaGetSymbolAddress((void**)&vec, g_vec);
    cudaGetSymbolAddress((void**)&h1, g_h1);
    cudaGetSymbolAddress((void**)&enc, g_enc);
    cudaGetSymbolAddress((void**)&xpart, g_xpart);
    cudaGetSymbolAddress((void**)&hA, g_h);
    cudaGetSymbolAddress((void**)&hB, g_hB);
    cudaGetSymbolAddress((void**)&bsum, g_bsum);
    cudaGetSymbolAddress((void**)&rpart, g_rpart);
    cudaGetSymbolAddress((void**)&wihR, g_wihR);
    cudaGetSymbolAddress((void**)&whhR, g_whhR);
    cudaGetSymbolAddress((void**)&p1R, g_p1R);
    cudaGetSymbolAddress((void**)&p2R, g_p2R);

    // 0: topk, 1: prep, 2: projgather, 3: agg_gate
    topk_kernel<<<NUNITS, 128>>>(
        qry, sup, q_l1, q_deg_l, q_r1, q_deg_r, s_l1, s_deg_l, s_r1, s_deg_r, emb);
    prep_kernel<<<149, 256>>>(gcn_w_w, b_ih, b_hh, (float*)d_out);
    projgather_kernel<<<PTILES, 256>>>(emb, gcn_w_b, gcn_b);
    agg_gate_kernel<<<(NUNITS + AW * AUPW - 1) / (AW * AUPW), 256>>>(
        qry, sup, q_l1, q_deg_l, q_r1, q_deg_r, s_l1, s_deg_l, s_r1, s_deg_r,
        emb, g1_w, g1_b, ln1_g, ln1_b, g2_w, g2_b, gate_temp);
    roundA_kernel<<<512, 256>>>(w_ih, w_hh);
    roundB_kernel<<<(DI * DM + DM * DI) / 4 / 256, 256>>>(se_p1_w, se_p2_w);

    // support encoder
    gemm_v3<64, 0><<<dim3(DI / 128, (NROWS + 63) / 64), 256>>>(
        vec, DM, p1R, DM, se_p1_b, nullptr, nullptr, h1, DI, NROWS, DI, DM, 1, 1, nullptr, 0);
    gemm_v3<64, 0><<<dim3(DM / 128, (NROWS + 63) / 64), 256>>>(
        h1, DI, p2R, DI, se_p2_b, nullptr, nullptr, enc, DM, NROWS, DM, DI, 0, 0, nullptr, 0);
    ln_kernel<<<NROWS, 256>>>(se_ln_g, se_ln_b);

    rpart_kernel<<<GR / 256, 256>>>(w_hh);

    // step 1: xpart GEMM + fused cell (c=0) -> hA
    gemm_v3<128, 1><<<dim3(GR / 128, NB / 128), 256>>>(
        enc, DM, wihR, DM, bsum, nullptr, nullptr, xpart, GR, NB, GR, DM, 0, 0, hA, 0);

    // steps 2..4: gates GEMM + fused cell; last step fuses final dot into d_out
    float* hin = hA; float* hout = hB;
    for (int s = 0; s < 3; s++) {
        int last = (s == 2);
        gemm_v3<128, 2><<<dim3(GR / 128, NB / 128), 256>>>(
            hin, DM, whhR, DM, nullptr, xpart, rpart, xpart, GR, NB, GR, DM, 0, 0,
            last ? (float*)d_out : hout, last);
        float* t = hin; hin = hout; hout = t;
    }
}

// round 17
// speedup vs baseline: 1.1427x; 1.1232x over previous
#include <cuda_runtime.h>
#include <cuda_bf16.h>
#include <cstdint>
#include <math.h>

#define NB 4096
#define NSUP 5
#define NROWS (NB + NSUP)
#define ED 128
#define DM 256
#define DI 512
#define LH 512
#define GR 1024
#define PADI 200000
#define MAXK 64
#define TOPK 10
#define NUNITS (2 * NB + 2 * NSUP)   // 8202
#define PROWS (NUNITS * TOPK)        // 82020
#define PROWS_PAD 82080
#define PTILES ((PROWS + 127) / 128) // 641
#define KPAD 36
#define KPADH 40                     // bf16 units per smem row (80 B)

// ------------------- device scratch -------------------
__device__ float g_vec[NROWS * DM];
__device__ float g_h1[NROWS * DI];
__device__ float g_enc[NROWS * DM];
__device__ __nv_bfloat16 g_encH[NROWS * DM];
__device__ float g_supg[DM];
__device__ float g_rpart[GR];
__device__ float g_bsum[GR];
__device__ float g_xpart[(size_t)NB * GR];
__device__ __nv_bfloat16 g_hH[(size_t)NB * DM];
__device__ __nv_bfloat16 g_hBH[(size_t)NB * DM];
__device__ float g_c[(size_t)NB * DM];
__device__ __nv_bfloat16 g_wihH[GR * DM];
__device__ __nv_bfloat16 g_whhH[GR * DM];
__device__ float g_p1R[DI * DM];
__device__ float g_p2R[DM * DI];
__device__ float g_gcnR[ED * DM];
__device__ int   g_rowids[PROWS_PAD * 2];
__device__ int4  g_uinfo[8208];
__device__ float g_proj[(size_t)(PTILES * 128) * ED];

__device__ __forceinline__ float warp_sum(float v) {
#pragma unroll
    for (int o = 16; o; o >>= 1) v += __shfl_xor_sync(0xffffffffu, v, o);
    return v;
}
__device__ __forceinline__ float sigf(float x) { return 1.0f / (1.0f + expf(-x)); }
__device__ __forceinline__ float tf32r(float v) {
    uint32_t r;
    asm("cvt.rna.tf32.f32 %0, %1;" : "=r"(r) : "f"(v));
    return __uint_as_float(r);
}
__device__ __forceinline__ float4 tf32r4(float4 v) {
    v.x = tf32r(v.x); v.y = tf32r(v.y); v.z = tf32r(v.z); v.w = tf32r(v.w);
    return v;
}
__device__ __forceinline__ void mma_tf32(float* c, const uint32_t* a, const uint32_t* b) {
    asm volatile(
        "mma.sync.aligned.m16n8k8.row.col.f32.tf32.tf32.f32 "
        "{%0,%1,%2,%3}, {%4,%5,%6,%7}, {%8,%9}, {%0,%1,%2,%3};"
        : "+f"(c[0]), "+f"(c[1]), "+f"(c[2]), "+f"(c[3])
        : "r"(a[0]), "r"(a[1]), "r"(a[2]), "r"(a[3]), "r"(b[0]), "r"(b[1]));
}
__device__ __forceinline__ void mma_bf16(float* c, const uint32_t* a, const uint32_t* b) {
    asm volatile(
        "mma.sync.aligned.m16n8k16.row.col.f32.bf16.bf16.f32 "
        "{%0,%1,%2,%3}, {%4,%5,%6,%7}, {%8,%9}, {%0,%1,%2,%3};"
        : "+f"(c[0]), "+f"(c[1]), "+f"(c[2]), "+f"(c[3])
        : "r"(a[0]), "r"(a[1]), "r"(a[2]), "r"(a[3]), "r"(b[0]), "r"(b[1]));
}
__device__ __forceinline__ void cp_async16(uint32_t s, const void* g, int sz) {
    asm volatile("cp.async.cg.shared.global [%0], [%1], 16, %2;\n"
                 :: "r"(s), "l"(g), "r"(sz));
}
__device__ __forceinline__ void cp_commit() { asm volatile("cp.async.commit_group;\n"); }
__device__ __forceinline__ void cp_wait1() { asm volatile("cp.async.wait_group 1;\n"); }
__device__ __forceinline__ void cp_wait0() { asm volatile("cp.async.wait_group 0;\n"); }

__device__ __forceinline__ int permN(int n) {
    return (((n >> 3) & 3) << 9) + ((n >> 5) << 3) + (n & 7);
}

__device__ __forceinline__ void unit_decode(
    int ur,
    const int* qry, const int* sup,
    const int* q_l1, const int* q_deg_l, const int* q_r1, const int* q_deg_r,
    const int* s_l1, const int* s_deg_l, const int* s_r1, const int* s_deg_r,
    const int** conn, int* deg, int* selfid, size_t* outoff) {
    if (ur < NB) {
        *conn = q_l1 + ur * MAXK * 2; *deg = q_deg_l[ur];
        *selfid = qry[ur * 2 + 0]; *outoff = (size_t)ur * DM;
    } else if (ur < 2 * NB) {
        int b = ur - NB;
        *conn = q_r1 + b * MAXK * 2; *deg = q_deg_r[b];
        *selfid = qry[b * 2 + 1]; *outoff = (size_t)b * DM + ED;
    } else if (ur < 2 * NB + NSUP) {
        int i = ur - 2 * NB;
        *conn = s_l1 + i * MAXK * 2; *deg = s_deg_l[i];
        *selfid = sup[i * 2 + 0]; *outoff = (size_t)(NB + i) * DM;
    } else {
        int i = ur - 2 * NB - NSUP;
        *conn = s_r1 + i * MAXK * 2; *deg = s_deg_r[i];
        *selfid = sup[i * 2 + 1]; *outoff = (size_t)(NB + i) * DM + ED;
    }
}

// ------------------- prep kernels -------------------
__global__ void prep_kernel(const float* __restrict__ gcn,
                            const float* __restrict__ b_ih,
                            const float* __restrict__ b_hh,
                            float* __restrict__ out) {
    int t = threadIdx.x, b = blockIdx.x;
    if (b < 128) {
        int i = b * 256 + t;
        g_gcnR[i] = tf32r(gcn[i]);
    } else if (b < 132) {
        int n = (b - 128) * 256 + t;
        int p = permN(n);
        g_bsum[n] = b_ih[p] + b_hh[p];
    } else if (b == 132) {
        if (t < (PROWS_PAD - PROWS) * 2) g_rowids[PROWS * 2 + t] = 0;
    } else {
        int i = (b - 133) * 256 + t;
        if (i < NB) out[i] = 0.f;
    }
}
__global__ void roundA_kernel(const float* __restrict__ w_ih, const float* __restrict__ w_hh) {
    int t = threadIdx.x, b = blockIdx.x;
    int n = (b & 255) * 4 + (t >> 6);
    int q = t & 63;
    int p = permN(n);
    float4 v;
    __nv_bfloat16* dst;
    if (b < 256) {
        v = ((const float4*)(w_ih + p * DM))[q];
        dst = g_wihH + n * DM + q * 4;
    } else {
        v = ((const float4*)(w_hh + (size_t)p * LH))[q];
        dst = g_whhH + n * DM + q * 4;
    }
    __nv_bfloat162 lo = __floats2bfloat162_rn(v.x, v.y);
    __nv_bfloat162 hi = __floats2bfloat162_rn(v.z, v.w);
    *(__nv_bfloat162*)(dst) = lo;
    *(__nv_bfloat162*)(dst + 2) = hi;
}
__global__ void roundB_kernel(const float* __restrict__ p1, const float* __restrict__ p2) {
    int i = blockIdx.x * 256 + threadIdx.x;
    if (i < DI * DM / 4) {
        ((float4*)g_p1R)[i] = tf32r4(((const float4*)p1)[i]);
    } else {
        int j = i - DI * DM / 4;
        ((float4*)g_p2R)[j] = tf32r4(((const float4*)p2)[j]);
    }
}

// ------------------- phase 1: sims + top-10 -------------------
__global__ void __launch_bounds__(128)
topk_kernel(const int* __restrict__ qry, const int* __restrict__ sup,
            const int* __restrict__ q_l1, const int* __restrict__ q_deg_l,
            const int* __restrict__ q_r1, const int* __restrict__ q_deg_r,
            const int* __restrict__ s_l1, const int* __restrict__ s_deg_l,
            const int* __restrict__ s_r1, const int* __restrict__ s_deg_r,
            const float* __restrict__ emb) {
    __shared__ float s_selfn[ED];
    __shared__ float s_sim[MAXK];
    __shared__ int s_rel[MAXK], s_ent[MAXK];
    __shared__ float s_red[4];
    __shared__ float s_sc[1];

    int unit = blockIdx.x, tid = threadIdx.x;
    int lane = tid & 31, warp = tid >> 5;

    const int* conn; int deg, selfid; size_t outoff;
    unit_decode(unit, qry, sup, q_l1, q_deg_l, q_r1, q_deg_r,
                s_l1, s_deg_l, s_r1, s_deg_r, &conn, &deg, &selfid, &outoff);

    float se = emb[(size_t)selfid * ED + tid];
    float ss = warp_sum(se * se);
    if (lane == 0) s_red[warp] = ss;
    __syncthreads();
    if (tid == 0)
        s_sc[0] = 1.0f / fmaxf(sqrtf(s_red[0] + s_red[1] + s_red[2] + s_red[3]), 1e-12f);
    __syncthreads();
    s_selfn[tid] = se * s_sc[0];
    __syncthreads();

    int gid = lane >> 3, gl = lane & 7;
    float4 sn[4];
#pragma unroll
    for (int q = 0; q < 4; q++) sn[q] = ((const float4*)s_selfn)[gl + 8 * q];

#pragma unroll
    for (int jt = 0; jt < 4; jt++) {
        int j = warp * 16 + jt * 4 + gid;
        int2 ids = ((const int2*)conn)[j];
        const float4* er = (const float4*)(emb + (size_t)ids.y * ED);
        float dot = 0.f, sq = 0.f;
#pragma unroll
        for (int q = 0; q < 4; q++) {
            float4 e = er[gl + 8 * q];
            dot += e.x * sn[q].x + e.y * sn[q].y + e.z * sn[q].z + e.w * sn[q].w;
            sq += e.x * e.x + e.y * e.y + e.z * e.z + e.w * e.w;
        }
#pragma unroll
        for (int o = 4; o; o >>= 1) {
            unsigned long long v =
                ((unsigned long long)__float_as_uint(sq) << 32) | __float_as_uint(dot);
            unsigned long long w = __shfl_xor_sync(0xffffffffu, v, o);
            dot += __uint_as_float((uint32_t)w);
            sq += __uint_as_float((uint32_t)(w >> 32));
        }
        if (gl == 0) {
            float sim = dot / fmaxf(sqrtf(sq), 1e-12f);
            if (ids.x == PADI) sim -= 1e9f;
            s_sim[j] = sim; s_rel[j] = ids.x; s_ent[j] = ids.y;
        }
    }
    __syncthreads();

    if (warp == 0) {
        float v0 = s_sim[lane], v1 = s_sim[lane + 32];
        int nv = 0, mask = 0;
#pragma unroll
        for (int t = 0; t < TOPK; t++) {
            float mv = v0; int mi = lane;
            if (v1 > mv) { mv = v1; mi = lane + 32; }
#pragma unroll
            for (int o = 16; o; o >>= 1) {
                float ov = __shfl_xor_sync(0xffffffffu, mv, o);
                int oi = __shfl_xor_sync(0xffffffffu, mi, o);
                if (ov > mv || (ov == mv && oi < mi)) { mv = ov; mi = oi; }
            }
            if (lane == 0) {
                int rel = s_rel[mi], ent = s_ent[mi];
                g_rowids[(unit * TOPK + t) * 2 + 0] = rel;
                g_rowids[(unit * TOPK + t) * 2 + 1] = ent;
                if (rel == PADI) mask |= (1 << t); else nv++;
            }
            if (mi == lane) v0 = -3.0e38f;
            if (mi == lane + 32) v1 = -3.0e38f;
        }
        if (lane == 0) g_uinfo[unit] = make_int4(selfid, deg, nv, mask);
    }
}

// ------------------- phase 2: gathered proj GEMM (tf32, R12 pipeline) -------------------
__global__ void __launch_bounds__(256, 2)
projgather_kernel(const float* __restrict__ emb,
                  const float* __restrict__ gcn_w_b,
                  const float* __restrict__ gcn_b) {
    __shared__ float As[3][128][KPAD];
    __shared__ float Bs[3][128][KPAD];
    __shared__ int2 s_ids[128];

    int tid = threadIdx.x;
    int m0 = blockIdx.x << 7;
    int lane = tid & 31, warp = tid >> 5;
    int wm = warp >> 2, wn = warp & 3;
    int r = lane >> 2, cq = lane & 3;

    uint32_t sA = (uint32_t)__cvta_generic_to_shared(&As[0][0][0]);
    uint32_t sB = (uint32_t)__cvta_generic_to_shared(&Bs[0][0][0]);
    const uint32_t strAB = 128 * KPAD * 4;

    if (tid < 128) s_ids[tid] = ((const int2*)g_rowids)[m0 + tid];
    __syncthreads();

    float acc[4][4][4];
#pragma unroll
    for (int i = 0; i < 4; i++)
#pragma unroll
        for (int j = 0; j < 4; j++)
#pragma unroll
            for (int q = 0; q < 4; q++) acc[i][j][q] = 0.f;

    auto stage = [&](int buf, int k0) {
        bool lo = (k0 < ED);
#pragma unroll
        for (int i = 0; i < 4; i++) {
            int seg = tid + i * 256;
            int row = seg >> 3, k4 = (seg & 7) << 2;
            int2 ids = s_ids[row];
            const float* srcA = emb + (size_t)(lo ? ids.x : ids.y) * ED
                                + (lo ? k0 : k0 - ED) + k4;
            cp_async16(sA + buf * strAB + (row * KPAD + k4) * 4, srcA, 16);
            cp_async16(sB + buf * strAB + (row * KPAD + k4) * 4,
                       g_gcnR + row * DM + k0 + k4, 16);
        }
        cp_commit();
    };

    stage(0, 0);
    stage(1, 32);
    int buf = 0;
    for (int kt = 0; kt < 8; kt++) {
        if (kt == 7) cp_wait0(); else cp_wait1();
        __syncthreads();

        const float (*Ab)[KPAD] = As[buf];
        const float (*Bb)[KPAD] = Bs[buf];
#pragma unroll
        for (int ks = 0; ks < 4; ks++) {
            int kb = ks * 8;
            uint32_t a[4][4];
#pragma unroll
            for (int am = 0; am < 4; am++) {
                int row = wm * 64 + am * 16 + r;
                a[am][0] = __float_as_uint(Ab[row][kb + cq]);
                a[am][1] = __float_as_uint(Ab[row + 8][kb + cq]);
                a[am][2] = __float_as_uint(Ab[row][kb + cq + 4]);
                a[am][3] = __float_as_uint(Ab[row + 8][kb + cq + 4]);
            }
            uint32_t b[4][2];
#pragma unroll
            for (int an = 0; an < 4; an++) {
                int nrow = wn * 32 + an * 8 + r;
                b[an][0] = __float_as_uint(Bb[nrow][kb + cq]);
                b[an][1] = __float_as_uint(Bb[nrow][kb + cq + 4]);
            }
#pragma unroll
            for (int am = 0; am < 4; am++)
#pragma unroll
                for (int an = 0; an < 4; an++)
                    mma_tf32(acc[am][an], a[am], b[an]);
        }
        if (kt + 2 < 8) stage(buf + 2 >= 3 ? buf - 1 : buf + 2, (kt + 2) << 5);
        buf = (buf == 2) ? 0 : buf + 1;
    }

#pragma unroll
    for (int am = 0; am < 4; am++) {
        int rw0 = m0 + wm * 64 + am * 16 + r;
        int rw1 = rw0 + 8;
#pragma unroll
        for (int an = 0; an < 4; an++) {
            int col = wn * 32 + an * 8 + cq * 2;
            float b0 = gcn_w_b[col] + gcn_b[col];
            float b1 = gcn_w_b[col + 1] + gcn_b[col + 1];
            if (rw0 < PROWS) {
                float v0 = acc[am][an][0] + b0;
                float v1 = acc[am][an][1] + b1;
                v0 = v0 > 0.f ? v0 : 0.01f * v0;
                v1 = v1 > 0.f ? v1 : 0.01f * v1;
                g_proj[(size_t)rw0 * ED + col] = v0;
                g_proj[(size_t)rw0 * ED + col + 1] = v1;
            }
            if (rw1 < PROWS) {
                float v2 = acc[am][an][2] + b0;
                float v3 = acc[am][an][3] + b1;
                v2 = v2 > 0.f ? v2 : 0.01f * v2;
                v3 = v3 > 0.f ? v3 : 0.01f * v3;
                g_proj[(size_t)rw1 * ED + col] = v2;
                g_proj[(size_t)rw1 * ED + col + 1] = v3;
            }
        }
    }
}

// ------------------- phase 3: warp-per-unit agg + gate MLP + output -------------------
#define AW 8
#define AUPW 4
__global__ void __launch_bounds__(256)
agg_gate_kernel(const int* __restrict__ qry, const int* __restrict__ sup,
                const int* __restrict__ q_l1, const int* __restrict__ q_deg_l,
                const int* __restrict__ q_r1, const int* __restrict__ q_deg_r,
                const int* __restrict__ s_l1, const int* __restrict__ s_deg_l,
                const int* __restrict__ s_r1, const int* __restrict__ s_deg_r,
                const float* __restrict__ emb,
                const float* __restrict__ g1_w, const float* __restrict__ g1_b,
                const float* __restrict__ ln1_g, const float* __restrict__ ln1_b,
                const float* __restrict__ g2_w, const float* __restrict__ g2_b,
                const float* __restrict__ gate_temp) {
    __shared__ float4 s_g1[64 * 32];
    __shared__ float4 s_agg[AW][33];
    __shared__ float s_b[64], s_lg[64], s_lb[64], s_g2[64];
    __shared__ float s_scal[2];

    int tid = threadIdx.x;
    int lane = tid & 31, warp = tid >> 5;

#pragma unroll
    for (int i = 0; i < 8; i++) {
        int f = tid + i * 256;
        int d = f >> 5, g = f & 31;
        s_g1[d * 32 + (g ^ (d & 7))] = ((const float4*)g1_w)[f];
    }
    if (tid < 64) {
        s_b[tid] = g1_b[tid]; s_lg[tid] = ln1_g[tid];
        s_lb[tid] = ln1_b[tid]; s_g2[tid] = g2_w[tid];
    }
    if (tid == 0) {
        s_scal[0] = g2_b[0];
        s_scal[1] = 1.0f / fminf(fmaxf(gate_temp[0], 0.1f), 5.0f);
    }
    __syncthreads();

    float g2b = s_scal[0], invT = s_scal[1];

    for (int u = 0; u < AUPW; u++) {
        int unit = (blockIdx.x * AW + warp) * AUPW + u;
        if (unit >= NUNITS) break;
        int4 info = g_uinfo[unit];

        const float4* pr = (const float4*)(g_proj + (size_t)unit * TOPK * ED);
        float4 a = make_float4(0.f, 0.f, 0.f, 0.f);
#pragma unroll
        for (int j = 0; j < TOPK; j++) {
            if (!((info.w >> j) & 1)) {
                float4 p = pr[j * 32 + lane];
                a.x += p.x; a.y += p.y; a.z += p.z; a.w += p.w;
            }
        }
        float inv = 1.0f / fmaxf((float)info.z, 1.0f);
        a.x *= inv; a.y *= inv; a.z *= inv; a.w *= inv;
        s_agg[warp][lane] = a;
        __syncwarp();

        float y0 = s_b[lane], y1 = s_b[lane + 32];
        int sw = lane & 7;
        const float4* w0 = &s_g1[lane * 32];
        const float4* w1 = &s_g1[(lane + 32) * 32];
#pragma unroll
        for (int k = 0; k < 32; k++) {
            float4 av = s_agg[warp][k];
            float4 a0 = w0[k ^ sw];
            float4 a1 = w1[k ^ sw];
            y0 += av.x * a0.x + av.y * a0.y + av.z * a0.z + av.w * a0.w;
            y1 += av.x * a1.x + av.y * a1.y + av.z * a1.z + av.w * a1.w;
        }

        float s1 = warp_sum(y0 + y1);
        float s2 = warp_sum(y0 * y0 + y1 * y1);
        float mean = s1 * (1.0f / 64.0f);
        float var = s2 * (1.0f / 64.0f) - mean * mean;
        float rstd = rsqrtf(var + 1e-5f);
        float hv0 = fmaxf((y0 - mean) * rstd * s_lg[lane] + s_lb[lane], 0.f);
        float hv1 = fmaxf((y1 - mean) * rstd * s_lg[lane + 32] + s_lb[lane + 32], 0.f);
        float logit = warp_sum(hv0 * s_g2[lane] + hv1 * s_g2[lane + 32]) + g2b;
        float gate = 1.0f / (1.0f + expf(-logit * invT));
        if (info.y <= 0) gate = 0.f;

        const int* conn; int deg, selfid; size_t outoff;
        unit_decode(unit, qry, sup, q_l1, q_deg_l, q_r1, q_deg_r,
                    s_l1, s_deg_l, s_r1, s_deg_r, &conn, &deg, &selfid, &outoff);
        float4 e = ((const float4*)(emb + (size_t)info.x * ED))[lane];
        float4 o;
        o.x = tf32r(tanhf(e.x + gate * a.x));
        o.y = tf32r(tanhf(e.y + gate * a.y));
        o.z = tf32r(tanhf(e.z + gate * a.z));
        o.w = tf32r(tanhf(e.w + gate * a.w));
        *(float4*)(g_vec + outoff + lane * 4) = o;
        __syncwarp();
    }
}

// ------------------- TF32 GEMM (SE layers only) -------------------
template<int BMT>
__global__ void __launch_bounds__(256, 2)
gemm_v3(const float* __restrict__ A, int lda,
        const float* __restrict__ W, int ldw,
        const float* __restrict__ bias,
        float* __restrict__ C, int ldc,
        int M, int N, int K, int act, int roundOut) {
    constexpr int AMT = BMT / 32;
    constexpr int ASEG = BMT * 8 / 256;
    __shared__ float As[3][BMT][KPAD];
    __shared__ float Bs[3][128][KPAD];

    int tid = threadIdx.x;
    int m0 = blockIdx.y * BMT, n0 = blockIdx.x << 7;
    int lane = tid & 31, warp = tid >> 5;
    int wm = warp >> 2, wn = warp & 3;
    int r = lane >> 2, cq = lane & 3;

    uint32_t sA = (uint32_t)__cvta_generic_to_shared(&As[0][0][0]);
    uint32_t sB = (uint32_t)__cvta_generic_to_shared(&Bs[0][0][0]);
    const uint32_t strA = BMT * KPAD * 4;
    const uint32_t strB = 128 * KPAD * 4;

    float acc[AMT][4][4];
#pragma unroll
    for (int i = 0; i < AMT; i++)
#pragma unroll
        for (int j = 0; j < 4; j++)
#pragma unroll
            for (int q = 0; q < 4; q++) acc[i][j][q] = 0.f;

    int KT = K >> 5;

    auto stage = [&](int buf, int k0) {
#pragma unroll
        for (int i = 0; i < ASEG; i++) {
            int seg = tid + i * 256;
            int row = seg >> 3, k4 = (seg & 7) << 2;
            int m = m0 + row;
            cp_async16(sA + buf * strA + (row * KPAD + k4) * 4,
                       A + (size_t)m * lda + k0 + k4, m < M ? 16 : 0);
        }
#pragma unroll
        for (int i = 0; i < 4; i++) {
            int seg = tid + i * 256;
            int row = seg >> 3, k4 = (seg & 7) << 2;
            cp_async16(sB + buf * strB + (row * KPAD + k4) * 4,
                       W + (size_t)(n0 + row) * ldw + k0 + k4, 16);
        }
        cp_commit();
    };

    stage(0, 0);
    stage(1, 32);
    int buf = 0;
    for (int kt = 0; kt < KT; kt++) {
        if (kt == KT - 1) cp_wait0(); else cp_wait1();
        __syncthreads();

        const float (*Ab)[KPAD] = As[buf];
        const float (*Bb)[KPAD] = Bs[buf];
#pragma unroll
        for (int ks = 0; ks < 4; ks++) {
            int kb = ks * 8;
            uint32_t a[AMT][4];
#pragma unroll
            for (int am = 0; am < AMT; am++) {
                int row = wm * (AMT * 16) + am * 16 + r;
                a[am][0] = __float_as_uint(Ab[row][kb + cq]);
                a[am][1] = __float_as_uint(Ab[row + 8][kb + cq]);
                a[am][2] = __float_as_uint(Ab[row][kb + cq + 4]);
                a[am][3] = __float_as_uint(Ab[row + 8][kb + cq + 4]);
            }
            uint32_t b[4][2];
#pragma unroll
            for (int an = 0; an < 4; an++) {
                int nrow = wn * 32 + an * 8 + r;
                b[an][0] = __float_as_uint(Bb[nrow][kb + cq]);
                b[an][1] = __float_as_uint(Bb[nrow][kb + cq + 4]);
            }
#pragma unroll
            for (int am = 0; am < AMT; am++)
#pragma unroll
                for (int an = 0; an < 4; an++)
                    mma_tf32(acc[am][an], a[am], b[an]);
        }
        if (kt + 2 < KT) stage(buf + 2 >= 3 ? buf - 1 : buf + 2, (kt + 2) << 5);
        buf = (buf == 2) ? 0 : buf + 1;
    }

#pragma unroll
    for (int am = 0; am < AMT; am++) {
        int rw0 = m0 + wm * (AMT * 16) + am * 16 + r;
        int rw1 = rw0 + 8;
#pragma unroll
        for (int an = 0; an < 4; an++) {
            int col = n0 + wn * 32 + an * 8 + cq * 2;
            float add0 = bias[col], add1 = bias[col + 1];
            if (rw0 < M) {
                float v0 = acc[am][an][0] + add0;
                float v1 = acc[am][an][1] + add1;
                if (act) { v0 = fmaxf(v0, 0.f); v1 = fmaxf(v1, 0.f); }
                if (roundOut) { v0 = tf32r(v0); v1 = tf32r(v1); }
                C[(size_t)rw0 * ldc + col] = v0;
                C[(size_t)rw0 * ldc + col + 1] = v1;
            }
            if (rw1 < M) {
                float v2 = acc[am][an][2] + add0;
                float v3 = acc[am][an][3] + add1;
                if (act) { v2 = fmaxf(v2, 0.f); v3 = fmaxf(v3, 0.f); }
                if (roundOut) { v2 = tf32r(v2); v3 = tf32r(v3); }
                C[(size_t)rw1 * ldc + col] = v2;
                C[(size_t)rw1 * ldc + col + 1] = v3;
            }
        }
    }
}

// ------------------- BF16 GEMM + fused LSTM cell (recurrence family) -------------------
template<int MODE>
__global__ void __launch_bounds__(256, 2)
gemm_bf(const __nv_bfloat16* __restrict__ A,
        const __nv_bfloat16* __restrict__ W,
        const float* __restrict__ bias,
        const float* __restrict__ base,
        const float* __restrict__ rowv,
        float* __restrict__ C,
        void* __restrict__ hOut, int lastStep) {
    __shared__ __nv_bfloat16 As[3][128][KPADH];
    __shared__ __nv_bfloat16 Bs[3][128][KPADH];

    int tid = threadIdx.x;
    int m0 = blockIdx.y << 7, n0 = blockIdx.x << 7;
    int lane = tid & 31, warp = tid >> 5;
    int wm = warp >> 2, wn = warp & 3;
    int r = lane >> 2, cq = lane & 3;

    uint32_t sA = (uint32_t)__cvta_generic_to_shared(&As[0][0][0]);
    uint32_t sB = (uint32_t)__cvta_generic_to_shared(&Bs[0][0][0]);
    const uint32_t strAB = 128 * KPADH * 2;

    float acc[4][4][4];
#pragma unroll
    for (int i = 0; i < 4; i++)
#pragma unroll
        for (int j = 0; j < 4; j++)
#pragma unroll
            for (int q = 0; q < 4; q++) acc[i][j][q] = 0.f;

    auto stage = [&](int buf, int k0) {
#pragma unroll
        for (int i = 0; i < 2; i++) {
            int seg = tid + i * 256;
            int row = seg >> 2, ch = seg & 3;
            cp_async16(sA + buf * strAB + (row * KPADH + ch * 8) * 2,
                       A + (size_t)(m0 + row) * DM + k0 + ch * 8, 16);
            cp_async16(sB + buf * strAB + (row * KPADH + ch * 8) * 2,
                       W + (size_t)(n0 + row) * DM + k0 + ch * 8, 16);
        }
        cp_commit();
    };

    stage(0, 0);
    stage(1, 32);
    int buf = 0;
    for (int kt = 0; kt < 8; kt++) {
        if (kt == 7) cp_wait0(); else cp_wait1();
        __syncthreads();

        const __nv_bfloat16 (*Ab)[KPADH] = As[buf];
        const __nv_bfloat16 (*Bb)[KPADH] = Bs[buf];
#pragma unroll
        for (int ks = 0; ks < 2; ks++) {
            int kb = ks * 16;
            uint32_t a[4][4];
#pragma unroll
            for (int am = 0; am < 4; am++) {
                int row = wm * 64 + am * 16 + r;
                a[am][0] = *(const uint32_t*)&Ab[row][kb + 2 * cq];
                a[am][1] = *(const uint32_t*)&Ab[row + 8][kb + 2 * cq];
                a[am][2] = *(const uint32_t*)&Ab[row][kb + 2 * cq + 8];
                a[am][3] = *(const uint32_t*)&Ab[row + 8][kb + 2 * cq + 8];
            }
            uint32_t b[4][2];
#pragma unroll
            for (int an = 0; an < 4; an++) {
                int nrow = wn * 32 + an * 8 + r;
                b[an][0] = *(const uint32_t*)&Bb[nrow][kb + 2 * cq];
                b[an][1] = *(const uint32_t*)&Bb[nrow][kb + 2 * cq + 8];
            }
#pragma unroll
            for (int am = 0; am < 4; am++)
#pragma unroll
                for (int an = 0; an < 4; an++)
                    mma_bf16(acc[am][an], a[am], b[an]);
        }
        if (kt + 2 < 8) stage(buf + 2 >= 3 ? buf - 1 : buf + 2, (kt + 2) << 5);
        buf = (buf == 2) ? 0 : buf + 1;
    }

#pragma unroll
    for (int am = 0; am < 4; am++) {
        int rw0 = m0 + wm * 64 + am * 16 + r;
        int rw1 = rw0 + 8;
#pragma unroll
        for (int an = 0; an < 4; an++) {
            int col = n0 + wn * 32 + an * 8 + cq * 2;
            float add0 = 0.f, add1 = 0.f;
            if (bias) { add0 += bias[col]; add1 += bias[col + 1]; }
            if (rowv) { add0 += rowv[col]; add1 += rowv[col + 1]; }
            acc[am][an][0] += add0; acc[am][an][1] += add1;
            acc[am][an][2] += add0; acc[am][an][3] += add1;
            if (base) {
                acc[am][an][0] += base[(size_t)rw0 * GR + col];
                acc[am][an][1] += base[(size_t)rw0 * GR + col + 1];
                acc[am][an][2] += base[(size_t)rw1 * GR + col];
                acc[am][an][3] += base[(size_t)rw1 * GR + col + 1];
            }
        }
    }

    if (MODE == 1) {
#pragma unroll
        for (int am = 0; am < 4; am++) {
            int rw0 = m0 + wm * 64 + am * 16 + r;
            int rw1 = rw0 + 8;
#pragma unroll
            for (int an = 0; an < 4; an++) {
                int col = n0 + wn * 32 + an * 8 + cq * 2;
                C[(size_t)rw0 * GR + col] = acc[am][an][0];
                C[(size_t)rw0 * GR + col + 1] = acc[am][an][1];
                C[(size_t)rw1 * GR + col] = acc[am][an][2];
                C[(size_t)rw1 * GR + col + 1] = acc[am][an][3];
            }
        }
    }

    float cold[16], cv[16], hv[16];
    size_t cBase = ((size_t)(blockIdx.y * gridDim.x + blockIdx.x) * 256 + tid) * 16;
    if (MODE == 2) {
#pragma unroll
        for (int j = 0; j < 4; j++)
            *(float4*)&cold[j * 4] = *(const float4*)&g_c[cBase + j * 4];
    } else {
#pragma unroll
        for (int j = 0; j < 16; j++) cold[j] = 0.f;
    }
#pragma unroll
    for (int am = 0; am < 4; am++) {
#pragma unroll
        for (int hs = 0; hs < 2; hs++) {
#pragma unroll
            for (int e = 0; e < 2; e++) {
                int q = hs * 2 + e;
                int idx = am * 4 + hs * 2 + e;
                float iv = sigf(acc[am][0][q]);
                float fv = sigf(acc[am][1][q]);
                float gv = tanhf(acc[am][2][q]);
                float ov = sigf(acc[am][3][q]);
                float cn = fv * cold[idx] + iv * gv;
                cv[idx] = cn;
                hv[idx] = ov * tanhf(cn);
            }
        }
    }
    if (!lastStep) {
#pragma unroll
        for (int j = 0; j < 4; j++)
            *(float4*)&g_c[cBase + j * 4] = *(float4*)&cv[j * 4];
    }
    float* sh = (float*)&As[0][0][0];
    __syncthreads();
#pragma unroll
    for (int am = 0; am < 4; am++)
#pragma unroll
        for (int hs = 0; hs < 2; hs++)
#pragma unroll
            for (int e = 0; e < 2; e++) {
                int row_l = wm * 64 + am * 16 + r + hs * 8;
                int ul = wn * 8 + cq * 2 + e;
                sh[row_l * 33 + ul] = hv[am * 4 + hs * 2 + e];
            }
    __syncthreads();
    int row_l = tid >> 1, half = tid & 1;
    int ubase = n0 >> 2;
    size_t go = (size_t)(m0 + row_l) * DM + ubase + half * 16;
    const float* src = &sh[row_l * 33 + half * 16];
    if (!lastStep) {
        __nv_bfloat16* hp = (__nv_bfloat16*)hOut + go;
#pragma unroll
        for (int j = 0; j < 4; j++) {
            float4 ev = *(const float4*)(g_enc + go + j * 4);
            __nv_bfloat162 lo = __floats2bfloat162_rn(ev.x + src[j * 4 + 0],
                                                      ev.y + src[j * 4 + 1]);
            __nv_bfloat162 hi = __floats2bfloat162_rn(ev.z + src[j * 4 + 2],
                                                      ev.w + src[j * 4 + 3]);
            *(__nv_bfloat162*)(hp + j * 4) = lo;
            *(__nv_bfloat162*)(hp + j * 4 + 2) = hi;
        }
    } else {
        const float* sg = g_supg + ubase + half * 16;
        float p = 0.f;
#pragma unroll
        for (int j = 0; j < 16; j++)
            p += (g_enc[go + j] + src[j]) * sg[j];
        p += __shfl_down_sync(0xffffffffu, p, 1);
        if (half == 0) atomicAdd((float*)hOut + m0 + row_l, p);
    }
}

// ------------------- residual layernorm (+ bf16 copy) -------------------
__global__ void __launch_bounds__(256)
ln_kernel(const float* __restrict__ g, const float* __restrict__ b) {
    __shared__ float s_red[16];
    int row = blockIdx.x, t = threadIdx.x;
    float v = g_enc[(size_t)row * DM + t] + g_vec[(size_t)row * DM + t];
    float s1 = warp_sum(v), s2 = warp_sum(v * v);
    if ((t & 31) == 0) { s_red[t >> 5] = s1; s_red[8 + (t >> 5)] = s2; }
    __syncthreads();
    float S1 = 0.f, S2 = 0.f;
#pragma unroll
    for (int i = 0; i < 8; i++) { S1 += s_red[i]; S2 += s_red[8 + i]; }
    float mean = S1 * (1.0f / 256.0f);
    float var = S2 * (1.0f / 256.0f) - mean * mean;
    float o = (v - mean) * rsqrtf(var + 1e-5f) * g[t] + b[t];
    g_enc[(size_t)row * DM + t] = o;
    g_encH[(size_t)row * DM + t] = __float2bfloat16(o);
}

// rpart (supg computed in-block; block 0 publishes g_supg)
__global__ void rpart_kernel(const float* __restrict__ whh) {
    __shared__ float sg[DM];
    int t = threadIdx.x;
    float s = 0.f;
#pragma unroll
    for (int i = 0; i < NSUP; i++) s += g_enc[(size_t)(NB + i) * DM + t];
    s *= (1.0f / NSUP);
    sg[t] = s;
    if (blockIdx.x == 0) g_supg[t] = s;
    __syncthreads();
    int n = blockIdx.x * 256 + t;
    const float* row = whh + (size_t)permN(n) * LH + DM;
    float acc = 0.f;
    for (int k = 0; k < DM; k += 4) {
        float4 w = *(const float4*)(row + k);
        acc += w.x * sg[k] + w.y * sg[k + 1] + w.z * sg[k + 2] + w.w * sg[k + 3];
    }
    g_rpart[n] = acc;
}

// ------------------- host -------------------
extern "C" void kernel_launch(void* const* d_in, const int* in_sizes, int n_in,
                              void* d_out, int out_size) {
    const int* qry      = (const int*)d_in[0];
    const int* sup      = (const int*)d_in[1];
    const int* q_l1     = (const int*)d_in[2];
    const int* q_deg_l  = (const int*)d_in[3];
    const int* q_r1     = (const int*)d_in[4];
    const int* q_deg_r  = (const int*)d_in[5];
    const int* s_l1     = (const int*)d_in[6];
    const int* s_deg_l  = (const int*)d_in[7];
    const int* s_r1     = (const int*)d_in[8];
    const int* s_deg_r  = (const int*)d_in[9];
    const float* emb    = (const float*)d_in[10];
    const float* gcn_w_w = (const float*)d_in[11];
    const float* gcn_w_b = (const float*)d_in[12];
    const float* gcn_b   = (const float*)d_in[13];
    const float* g1_w    = (const float*)d_in[14];
    const float* g1_b    = (const float*)d_in[15];
    const float* ln1_g   = (const float*)d_in[16];
    const float* ln1_b   = (const float*)d_in[17];
    const float* g2_w    = (const float*)d_in[18];
    const float* g2_b    = (const float*)d_in[19];
    const float* gate_temp = (const float*)d_in[20];
    const float* se_p1_w = (const float*)d_in[21];
    const float* se_p1_b = (const float*)d_in[22];
    const float* se_p2_w = (const float*)d_in[23];
    const float* se_p2_b = (const float*)d_in[24];
    const float* se_ln_g = (const float*)d_in[25];
    const float* se_ln_b = (const float*)d_in[26];
    const float* w_ih    = (const float*)d_in[27];
    const float* w_hh    = (const float*)d_in[28];
    const float* b_ih    = (const float*)d_in[29];
    const float* b_hh    = (const float*)d_in[30];

    float *vec, *h1, *enc, *xpart, *bsum, *rpart;
    float *p1R, *p2R;
    __nv_bfloat16 *encH, *wihH, *whhH, *hA, *hB;
    cudaGetSymbolAddress((void**)&vec, g_vec);
    cudaGetSymbolAddress((void**)&h1, g_h1);
    cudaGetSymbolAddress((void**)&enc, g_enc);
    cudaGetSymbolAddress((void**)&xpart, g_xpart);
    cudaGetSymbolAddress((void**)&bsum, g_bsum);
    cudaGetSymbolAddress((void**)&rpart, g_rpart);
    cudaGetSymbolAddress((void**)&p1R, g_p1R);
    cudaGetSymbolAddress((void**)&p2R, g_p2R);
    cudaGetSymbolAddress((void**)&encH, g_encH);
    cudaGetSymbolAddress((void**)&wihH, g_wihH);
    cudaGetSymbolAddress((void**)&whhH, g_whhH);
    cudaGetSymbolAddress((void**)&hA, g_hH);
    cudaGetSymbolAddress((void**)&hB, g_hBH);

    // 0: topk, 1: prep, 2: projgather, 3: agg_gate
    topk_kernel<<<NUNITS, 128>>>(
        qry, sup, q_l1, q_deg_l, q_r1, q_deg_r, s_l1, s_deg_l, s_r1, s_deg_r, emb);
    prep_kernel<<<149, 256>>>(gcn_w_w, b_ih, b_hh, (float*)d_out);
    projgather_kernel<<<PTILES, 256>>>(emb, gcn_w_b, gcn_b);
    agg_gate_kernel<<<(NUNITS + AW * AUPW - 1) / (AW * AUPW), 256>>>(
        qry, sup, q_l1, q_deg_l, q_r1, q_deg_r, s_l1, s_deg_l, s_r1, s_deg_r,
        emb, g1_w, g1_b, ln1_g, ln1_b, g2_w, g2_b, gate_temp);
    roundA_kernel<<<512, 256>>>(w_ih, w_hh);
    roundB_kernel<<<(DI * DM + DM * DI) / 4 / 256, 256>>>(se_p1_w, se_p2_w);

    // support encoder (tf32)
    gemm_v3<64><<<dim3(DI / 128, (NROWS + 63) / 64), 256>>>(
        vec, DM, p1R, DM, se_p1_b, h1, DI, NROWS, DI, DM, 1, 1);
    gemm_v3<64><<<dim3(DM / 128, (NROWS + 63) / 64), 256>>>(
        h1, DI, p2R, DI, se_p2_b, enc, DM, NROWS, DM, DI, 0, 0);
    ln_kernel<<<NROWS, 256>>>(se_ln_g, se_ln_b);

    rpart_kernel<<<GR / 256, 256>>>(w_hh);

    // step 1: xpart = encH@WihH^T + bsum (bf16 mma), fused cell (c=0) -> hA
    gemm_bf<1><<<dim3(GR / 128, NB / 128), 256>>>(
        encH, wihH, bsum, nullptr, nullptr, xpart, hA, 0);

    // steps 2..4: gates = h@WhhH^T + xpart + rpart, fused cell; last fuses dot
    __nv_bfloat16* hin = hA; __nv_bfloat16* hout = hB;
    for (int s = 0; s < 3; s++) {
        int last = (s == 2);
        gemm_bf<2><<<dim3(GR / 128, NB / 128), 256>>>(
            hin, whhH, nullptr, xpart, rpart, nullptr,
            last ? (void*)d_out : (void*)hout, last);
        __nv_bfloat16* t = hin; hin = hout; hout = t;
    }
}